// round 1
// baseline (speedup 1.0000x reference)
#include <cuda_runtime.h>
#include <math.h>

// ---------------- problem constants ----------------
#define Bb   4
#define Ll   1024
#define Dd   512
#define Hh   8
#define Ee   64
#define DINc 1024
#define Nn   16
#define Rr   32
#define Mrows (Bb*Ll)          // 4096

// ---------------- scratch (device globals, no runtime alloc) ----------------
__device__ float g_q [Mrows*Dd];
__device__ float g_k [Mrows*Dd];
__device__ float g_v [Mrows*Dd];
__device__ float g_o [Mrows*Dd];
__device__ float g_t1[Mrows*Dd];
__device__ float g_x1[Mrows*Dd];
__device__ float g_xz[(size_t)Mrows*2*DINc];
__device__ float g_xc[(size_t)Mrows*DINc];
__device__ float g_db[Mrows*64];
__device__ float g_dt[(size_t)Mrows*DINc];
__device__ float g_ya[(size_t)Mrows*DINc];
__device__ float g_y [Mrows*Dd];

// ---------------- generic NN GEMM: C[M,N] = A[M,K]@W[K,N] (+bias)(+act) ----
// Tile: BM=128, BN=64, BK=16; 256 threads (16x16); 8x4 microtile/thread.
// act: 0 = none, 1 = softplus
__global__ __launch_bounds__(256) void gemm_nn(
    const float* __restrict__ A, int lda,
    const float* __restrict__ W, int ldw,
    const float* __restrict__ bias,
    float* __restrict__ C, int ldc,
    int K, int act)
{
    __shared__ float As[16][129];
    __shared__ float Ws[16][68];
    const int tx = threadIdx.x, ty = threadIdx.y;
    const int tid = ty*16 + tx;
    const int row0 = blockIdx.y * 128;
    const int col0 = blockIdx.x * 64;
    const int ka = tid & 15, ma = (tid >> 4) * 8;
    const int nb = tid & 63, kb = (tid >> 6) * 4;
    float acc[8][4];
#pragma unroll
    for (int i=0;i<8;i++)
#pragma unroll
        for (int j=0;j<4;j++) acc[i][j]=0.f;

    for (int k0 = 0; k0 < K; k0 += 16) {
#pragma unroll
        for (int i=0;i<8;i++)
            As[ka][ma+i] = A[(long)(row0+ma+i)*lda + k0 + ka];
#pragma unroll
        for (int i=0;i<4;i++)
            Ws[kb+i][nb] = W[(long)(k0+kb+i)*ldw + col0 + nb];
        __syncthreads();
#pragma unroll
        for (int k=0;k<16;k++) {
            float a[8], w[4];
#pragma unroll
            for (int i=0;i<8;i++) a[i] = As[k][ty + 16*i];
#pragma unroll
            for (int j=0;j<4;j++) w[j] = Ws[k][tx + 16*j];
#pragma unroll
            for (int i=0;i<8;i++)
#pragma unroll
                for (int j=0;j<4;j++)
                    acc[i][j] = fmaf(a[i], w[j], acc[i][j]);
        }
        __syncthreads();
    }
#pragma unroll
    for (int j=0;j<4;j++) {
        int c = col0 + tx + 16*j;
        float bv = bias ? bias[c] : 0.f;
#pragma unroll
        for (int i=0;i<8;i++) {
            int r = row0 + ty + 16*i;
            float vv = acc[i][j] + bv;
            if (act == 1) vv = (vv > 20.f) ? vv : log1pf(__expf(vv));
            C[(long)r*ldc + c] = vv;
        }
    }
}

// ---------------- scores: S[b,h,l,s] = sum_e q[b,l,h,e] k[b,s,h,e] * 0.125 --
__global__ __launch_bounds__(256) void scores_nt(
    const float* __restrict__ q, const float* __restrict__ kk,
    float* __restrict__ attn)
{
    __shared__ float As[16][129];
    __shared__ float Ws[16][68];
    const int bz = blockIdx.z;
    const float* A  = q  + (long)(bz>>3)*Ll*Dd + (bz&7)*Ee;
    const float* Bt = kk + (long)(bz>>3)*Ll*Dd + (bz&7)*Ee;
    float* C = attn + (long)bz*Ll*Ll;
    const int tx = threadIdx.x, ty = threadIdx.y;
    const int tid = ty*16 + tx;
    const int row0 = blockIdx.y * 128;
    const int col0 = blockIdx.x * 64;
    const int ka = tid & 15, ma = (tid >> 4) * 8;
    const int kb = tid & 15, nbb = (tid >> 4) * 4;
    float acc[8][4];
#pragma unroll
    for (int i=0;i<8;i++)
#pragma unroll
        for (int j=0;j<4;j++) acc[i][j]=0.f;

    for (int k0 = 0; k0 < Ee; k0 += 16) {
#pragma unroll
        for (int i=0;i<8;i++)
            As[ka][ma+i] = A[(long)(row0+ma+i)*Dd + k0 + ka];
#pragma unroll
        for (int i=0;i<4;i++)
            Ws[kb][nbb+i] = Bt[(long)(col0+nbb+i)*Dd + k0 + kb];
        __syncthreads();
#pragma unroll
        for (int k=0;k<16;k++) {
            float a[8], w[4];
#pragma unroll
            for (int i=0;i<8;i++) a[i] = As[k][ty + 16*i];
#pragma unroll
            for (int j=0;j<4;j++) w[j] = Ws[k][tx + 16*j];
#pragma unroll
            for (int i=0;i<8;i++)
#pragma unroll
                for (int j=0;j<4;j++)
                    acc[i][j] = fmaf(a[i], w[j], acc[i][j]);
        }
        __syncthreads();
    }
#pragma unroll
    for (int i=0;i<8;i++) {
        int r = row0 + ty + 16*i;
#pragma unroll
        for (int j=0;j<4;j++) {
            int c = col0 + tx + 16*j;
            C[(long)r*Ll + c] = acc[i][j] * 0.125f;
        }
    }
}

// ---------------- o[b,l,h,:] = attn[b,h,l,:] @ v[b,:,h,:] ------------------
__global__ __launch_bounds__(256) void attnv_nn(
    const float* __restrict__ attn, const float* __restrict__ v,
    float* __restrict__ o)
{
    __shared__ float As[16][129];
    __shared__ float Ws[16][68];
    const int bz = blockIdx.z;
    const float* A = attn + (long)bz*Ll*Ll;
    const float* W = v + (long)(bz>>3)*Ll*Dd + (bz&7)*Ee;
    float* C       = o + (long)(bz>>3)*Ll*Dd + (bz&7)*Ee;
    const int tx = threadIdx.x, ty = threadIdx.y;
    const int tid = ty*16 + tx;
    const int row0 = blockIdx.y * 128;
    const int ka = tid & 15, ma = (tid >> 4) * 8;
    const int nb = tid & 63, kb = (tid >> 6) * 4;
    float acc[8][4];
#pragma unroll
    for (int i=0;i<8;i++)
#pragma unroll
        for (int j=0;j<4;j++) acc[i][j]=0.f;

    for (int k0 = 0; k0 < Ll; k0 += 16) {
#pragma unroll
        for (int i=0;i<8;i++)
            As[ka][ma+i] = A[(long)(row0+ma+i)*Ll + k0 + ka];
#pragma unroll
        for (int i=0;i<4;i++)
            Ws[kb+i][nb] = W[(long)(k0+kb+i)*Dd + nb];
        __syncthreads();
#pragma unroll
        for (int k=0;k<16;k++) {
            float a[8], w[4];
#pragma unroll
            for (int i=0;i<8;i++) a[i] = As[k][ty + 16*i];
#pragma unroll
            for (int j=0;j<4;j++) w[j] = Ws[k][tx + 16*j];
#pragma unroll
            for (int i=0;i<8;i++)
#pragma unroll
                for (int j=0;j<4;j++)
                    acc[i][j] = fmaf(a[i], w[j], acc[i][j]);
        }
        __syncthreads();
    }
#pragma unroll
    for (int i=0;i<8;i++) {
        int r = row0 + ty + 16*i;
#pragma unroll
        for (int j=0;j<4;j++)
            C[(long)r*Dd + tx + 16*j] = acc[i][j];
    }
}

// ---------------- softmax over rows of length 1024 (in place) -------------
__global__ __launch_bounds__(256) void softmax_k(float* __restrict__ a)
{
    const long row = blockIdx.x;
    float* p = a + row * (long)Ll;
    const int tid = threadIdx.x;
    float v[4];
    float m = -1e30f;
#pragma unroll
    for (int i=0;i<4;i++){ v[i] = p[tid + 256*i]; m = fmaxf(m, v[i]); }
#pragma unroll
    for (int off=16; off; off>>=1) m = fmaxf(m, __shfl_xor_sync(0xffffffffu, m, off));
    __shared__ float sm[8], ss[8];
    const int w = tid >> 5, lane = tid & 31;
    if (lane==0) sm[w] = m;
    __syncthreads();
    m = sm[0];
#pragma unroll
    for (int i=1;i<8;i++) m = fmaxf(m, sm[i]);
    float s = 0.f;
#pragma unroll
    for (int i=0;i<4;i++){ v[i] = __expf(v[i]-m); s += v[i]; }
#pragma unroll
    for (int off=16; off; off>>=1) s += __shfl_xor_sync(0xffffffffu, s, off);
    if (lane==0) ss[w] = s;
    __syncthreads();
    s = 0.f;
#pragma unroll
    for (int i=0;i<8;i++) s += ss[i];
    const float inv = 1.f / s;
#pragma unroll
    for (int i=0;i<4;i++) p[tid + 256*i] = v[i] * inv;
}

// ---------------- out = LayerNorm(xa + xb) --------------------------------
__global__ __launch_bounds__(128) void add_ln(
    const float* __restrict__ xa, const float* __restrict__ xb,
    const float* __restrict__ g, const float* __restrict__ bt,
    float* __restrict__ out)
{
    const int row = blockIdx.x, tid = threadIdx.x;
    const float* pa = xa + (long)row*Dd;
    const float* pb = xb + (long)row*Dd;
    float v[4]; float s1=0.f, s2=0.f;
#pragma unroll
    for (int i=0;i<4;i++){ int c = tid + 128*i; v[i] = pa[c] + pb[c]; s1 += v[i]; s2 += v[i]*v[i]; }
#pragma unroll
    for (int off=16; off; off>>=1){
        s1 += __shfl_xor_sync(0xffffffffu, s1, off);
        s2 += __shfl_xor_sync(0xffffffffu, s2, off);
    }
    __shared__ float r1[4], r2[4];
    const int w = tid >> 5, lane = tid & 31;
    if (lane==0){ r1[w]=s1; r2[w]=s2; }
    __syncthreads();
    s1 = r1[0]+r1[1]+r1[2]+r1[3];
    s2 = r2[0]+r2[1]+r2[2]+r2[3];
    const float mean = s1 * (1.f/Dd);
    const float var  = s2 * (1.f/Dd) - mean*mean;
    const float rstd = rsqrtf(var + 1e-5f);
    float* po = out + (long)row*Dd;
#pragma unroll
    for (int i=0;i<4;i++){ int c = tid + 128*i; po[c] = (v[i]-mean)*rstd*g[c] + bt[c]; }
}

// ---------------- depthwise causal conv (K=4) + bias + silu ----------------
__global__ __launch_bounds__(256) void conv_silu_k(
    const float* __restrict__ xz, const float* __restrict__ w,
    const float* __restrict__ cb, float* __restrict__ xc)
{
    const long idx = (long)blockIdx.x*256 + threadIdx.x;  // over Mrows*DINc
    const int d = (int)(idx & (DINc-1));
    const long row = idx >> 10;
    const int l = (int)(row & (Ll-1));
    float acc = cb[d];
#pragma unroll
    for (int j=0;j<4;j++) {
        int ll = l - 3 + j;
        if (ll >= 0)
            acc = fmaf(xz[(row-3+j)*(2*DINc) + d], w[d*4+j], acc);
    }
    xc[idx] = acc / (1.f + __expf(-acc));   // silu
}

// ---------------- selective scan, fused with +xc*D and *silu(z) ------------
// block: 128 threads = 8 d-values x 16 states; grid: Bb * DINc/8 = 512
__global__ __launch_bounds__(128) void scan_k(
    const float* __restrict__ dt, const float* __restrict__ xc,
    const float* __restrict__ dbl, const float* __restrict__ xz,
    const float* __restrict__ Alog, const float* __restrict__ Dp,
    float* __restrict__ yact)
{
    const int tid = threadIdx.x;
    const int n  = tid & 15;
    const int dl = tid >> 4;
    const int b  = blockIdx.x >> 7;            // DINc/8 = 128 groups per batch
    const int d  = (blockIdx.x & 127)*8 + dl;
    const float Aa = -__expf(Alog[d*Nn + n]);
    const float Dv = Dp[d];
    float h = 0.f;
    const long base = (long)b * Ll;
    for (int t = 0; t < Ll; t++) {
        const long row = base + t;
        const float dtv = dt[row*DINc + d];
        const float xcv = xc[row*DINc + d];
        const float Bv  = dbl[row*64 + 32 + n];
        const float Cv  = dbl[row*64 + 48 + n];
        const float dA  = __expf(dtv * Aa);
        h = fmaf(h, dA, dtv * xcv * Bv);
        float p = h * Cv;
        p += __shfl_xor_sync(0xffffffffu, p, 8);
        p += __shfl_xor_sync(0xffffffffu, p, 4);
        p += __shfl_xor_sync(0xffffffffu, p, 2);
        p += __shfl_xor_sync(0xffffffffu, p, 1);
        if (n == 0) {
            const float z  = xz[row*(2*DINc) + DINc + d];
            const float sz = z / (1.f + __expf(-z));
            yact[row*DINc + d] = (p + xcv * Dv) * sz;
        }
    }
}

// ---------------- launch ----------------------------------------------------
extern "C" void kernel_launch(void* const* d_in, const int* in_sizes, int n_in,
                              void* d_out, int out_size)
{
    const float* x    = (const float*)d_in[0];
    const float* Wq   = (const float*)d_in[1];
    const float* bq   = (const float*)d_in[2];
    const float* Wk   = (const float*)d_in[3];
    const float* bk   = (const float*)d_in[4];
    const float* Wv   = (const float*)d_in[5];
    const float* bv   = (const float*)d_in[6];
    const float* Wo   = (const float*)d_in[7];
    const float* bo   = (const float*)d_in[8];
    const float* ln1g = (const float*)d_in[9];
    const float* ln1b = (const float*)d_in[10];
    const float* ln2g = (const float*)d_in[11];
    const float* ln2b = (const float*)d_in[12];
    const float* Win  = (const float*)d_in[13];
    const float* cw   = (const float*)d_in[14];
    const float* cb   = (const float*)d_in[15];
    const float* Wx   = (const float*)d_in[16];
    const float* Wdt  = (const float*)d_in[17];
    const float* bdt  = (const float*)d_in[18];
    const float* Alog = (const float*)d_in[19];
    const float* Dp   = (const float*)d_in[20];
    const float* Wout = (const float*)d_in[21];

    float* out  = (float*)d_out;
    float* attn = out + (size_t)Bb*Ll*Dd;     // output tuple order: (out, attn)

    float *q,*k,*v,*o,*t1,*x1,*xz,*xc,*db,*dtb,*ya,*y;
    cudaGetSymbolAddress((void**)&q,  g_q);
    cudaGetSymbolAddress((void**)&k,  g_k);
    cudaGetSymbolAddress((void**)&v,  g_v);
    cudaGetSymbolAddress((void**)&o,  g_o);
    cudaGetSymbolAddress((void**)&t1, g_t1);
    cudaGetSymbolAddress((void**)&x1, g_x1);
    cudaGetSymbolAddress((void**)&xz, g_xz);
    cudaGetSymbolAddress((void**)&xc, g_xc);
    cudaGetSymbolAddress((void**)&db, g_db);
    cudaGetSymbolAddress((void**)&dtb,g_dt);
    cudaGetSymbolAddress((void**)&ya, g_ya);
    cudaGetSymbolAddress((void**)&y,  g_y);

    dim3 blk(16,16);

    // QKV projections
    gemm_nn<<<dim3(Dd/64, Mrows/128), blk>>>(x, Dd, Wq, Dd, bq, q, Dd, Dd, 0);
    gemm_nn<<<dim3(Dd/64, Mrows/128), blk>>>(x, Dd, Wk, Dd, bk, k, Dd, Dd, 0);
    gemm_nn<<<dim3(Dd/64, Mrows/128), blk>>>(x, Dd, Wv, Dd, bv, v, Dd, Dd, 0);
    // attention: raw scores -> in-place softmax (final attn output) -> attn@V
    scores_nt<<<dim3(Ll/64, Ll/128, Bb*Hh), blk>>>(q, k, attn);
    softmax_k<<<Bb*Hh*Ll, 256>>>(attn);
    attnv_nn<<<dim3(1, Ll/128, Bb*Hh), blk>>>(attn, v, o);
    // o @ Wo + bo ; x1 = LN(x + .)
    gemm_nn<<<dim3(Dd/64, Mrows/128), blk>>>(o, Dd, Wo, Dd, bo, t1, Dd, Dd, 0);
    add_ln<<<Mrows, 128>>>(x, t1, ln1g, ln1b, x1);
    // mamba in-proj
    gemm_nn<<<dim3(2*DINc/64, Mrows/128), blk>>>(x1, Dd, Win, 2*DINc, nullptr, xz, 2*DINc, Dd, 0);
    // depthwise conv + silu
    conv_silu_k<<<(Mrows*DINc)/256, 256>>>(xz, cw, cb, xc);
    // dbl = xc @ Wx
    gemm_nn<<<dim3(1, Mrows/128), blk>>>(xc, DINc, Wx, 64, nullptr, db, 64, DINc, 0);
    // dt = softplus(dbl[:, :32] @ Wdt + bdt)
    gemm_nn<<<dim3(DINc/64, Mrows/128), blk>>>(db, 64, Wdt, DINc, bdt, dtb, DINc, Rr, 1);
    // selective scan (+ xc*D, * silu(z))
    scan_k<<<Bb*(DINc/8), 128>>>(dtb, xc, db, xz, Alog, Dp, ya);
    // out-proj + final LN
    gemm_nn<<<dim3(Dd/64, Mrows/128), blk>>>(ya, DINc, Wout, Dd, nullptr, y, Dd, DINc, 0);
    add_ln<<<Mrows, 128>>>(x1, y, ln2g, ln2b, out);

    (void)in_sizes; (void)n_in; (void)out_size;
}

// round 4
// speedup vs baseline: 1.2421x; 1.2421x over previous
#include <cuda_runtime.h>
#include <math.h>

// ---------------- problem constants ----------------
#define Bb   4
#define Ll   1024
#define Dd   512
#define Hh   8
#define Ee   64
#define DINc 1024
#define Nn   16
#define Rr   32
#define Mrows (Bb*Ll)          // 4096

// ---------------- scratch (device globals, no runtime alloc) ----------------
__device__ float g_q [Mrows*Dd];
__device__ float g_k [Mrows*Dd];
__device__ float g_v [Mrows*Dd];
__device__ float g_o [Mrows*Dd];
__device__ float g_t1[Mrows*Dd];
__device__ float g_x1[Mrows*Dd];
__device__ float g_xz[(size_t)Mrows*2*DINc];
__device__ float g_xc[(size_t)Mrows*DINc];
__device__ float g_db[Mrows*64];
__device__ float g_dt[(size_t)Mrows*DINc];
__device__ float g_ya[(size_t)Mrows*DINc];
__device__ float g_y [Mrows*Dd];

// ================= 128x128 double-buffered SGEMM ===========================
// C[M,N] = A[M,K] @ W[K,N] (+bias). BM=BN=128, BK=8, 256 threads, 8x8 micro.
__global__ __launch_bounds__(256) void gemm128(
    const float* __restrict__ A, int lda,
    const float* __restrict__ W, int ldw,
    const float* __restrict__ bias,
    float* __restrict__ C, int ldc, int K)
{
    __shared__ float As[2][8][128];
    __shared__ float Bs[2][8][128];
    const int tid = threadIdx.x;
    const int row0 = blockIdx.y * 128;
    const int col0 = blockIdx.x * 128;
    const int ar = tid >> 1;            // 0..127
    const int ac = (tid & 1) * 4;       // 0 or 4
    const int br = tid >> 5;            // 0..7
    const int bc = (tid & 31) * 4;      // 0..124
    const int tm = (tid & 15) * 8;
    const int tn = (tid >> 4) * 8;

    float acc[8][8];
#pragma unroll
    for (int i=0;i<8;i++)
#pragma unroll
        for (int j=0;j<8;j++) acc[i][j]=0.f;

    float4 a4 = *(const float4*)(A + (long)(row0+ar)*lda + ac);
    float4 b4 = *(const float4*)(W + (long)br*ldw + col0 + bc);
    As[0][ac+0][ar]=a4.x; As[0][ac+1][ar]=a4.y; As[0][ac+2][ar]=a4.z; As[0][ac+3][ar]=a4.w;
    *(float4*)&Bs[0][br][bc] = b4;
    __syncthreads();

    int buf = 0;
    for (int k0 = 0; k0 < K; k0 += 8) {
        const bool more = (k0 + 8) < K;
        if (more) {
            a4 = *(const float4*)(A + (long)(row0+ar)*lda + k0 + 8 + ac);
            b4 = *(const float4*)(W + (long)(k0+8+br)*ldw + col0 + bc);
        }
#pragma unroll
        for (int k=0;k<8;k++){
            float a[8], b[8];
#pragma unroll
            for (int i=0;i<8;i++) a[i]=As[buf][k][tm+i];
#pragma unroll
            for (int j=0;j<8;j++) b[j]=Bs[buf][k][tn+j];
#pragma unroll
            for (int i=0;i<8;i++)
#pragma unroll
                for (int j=0;j<8;j++) acc[i][j]=fmaf(a[i],b[j],acc[i][j]);
        }
        buf ^= 1;
        if (more) {
            As[buf][ac+0][ar]=a4.x; As[buf][ac+1][ar]=a4.y;
            As[buf][ac+2][ar]=a4.z; As[buf][ac+3][ar]=a4.w;
            *(float4*)&Bs[buf][br][bc] = b4;
        }
        __syncthreads();
    }

    float bv[8];
#pragma unroll
    for (int j=0;j<8;j++) bv[j] = bias ? bias[col0+tn+j] : 0.f;
#pragma unroll
    for (int i=0;i<8;i++){
        float4 o1 = make_float4(acc[i][0]+bv[0], acc[i][1]+bv[1], acc[i][2]+bv[2], acc[i][3]+bv[3]);
        float4 o2 = make_float4(acc[i][4]+bv[4], acc[i][5]+bv[5], acc[i][6]+bv[6], acc[i][7]+bv[7]);
        float* p = C + (long)(row0+tm+i)*ldc + col0 + tn;
        *(float4*)(p)   = o1;
        *(float4*)(p+4) = o2;
    }
}

// ============ scores: S = q @ k^T * 0.125, per (b,h) =======================
// 128x128 tile, BK=8, double-buffered; B-operand loaded transposed.
__global__ __launch_bounds__(256) void scores128(
    const float* __restrict__ q, const float* __restrict__ kk,
    float* __restrict__ attn)
{
    __shared__ float As[2][8][128];
    __shared__ float Bs[2][8][128];
    const int bz = blockIdx.z;
    const float* A  = q  + (long)(bz>>3)*Ll*Dd + (bz&7)*Ee;
    const float* Bt = kk + (long)(bz>>3)*Ll*Dd + (bz&7)*Ee;
    float* C = attn + (long)bz*Ll*Ll;
    const int tid = threadIdx.x;
    const int row0 = blockIdx.y * 128;
    const int col0 = blockIdx.x * 128;
    const int ar = tid >> 1, ac = (tid & 1) * 4;
    const int tm = (tid & 15) * 8;
    const int tn = (tid >> 4) * 8;

    float acc[8][8];
#pragma unroll
    for (int i=0;i<8;i++)
#pragma unroll
        for (int j=0;j<8;j++) acc[i][j]=0.f;

    float4 a4 = *(const float4*)(A  + (long)(row0+ar)*Dd + ac);
    float4 b4 = *(const float4*)(Bt + (long)(col0+ar)*Dd + ac);
    As[0][ac+0][ar]=a4.x; As[0][ac+1][ar]=a4.y; As[0][ac+2][ar]=a4.z; As[0][ac+3][ar]=a4.w;
    Bs[0][ac+0][ar]=b4.x; Bs[0][ac+1][ar]=b4.y; Bs[0][ac+2][ar]=b4.z; Bs[0][ac+3][ar]=b4.w;
    __syncthreads();

    int buf = 0;
    for (int k0 = 0; k0 < Ee; k0 += 8) {
        const bool more = (k0 + 8) < Ee;
        if (more) {
            a4 = *(const float4*)(A  + (long)(row0+ar)*Dd + k0 + 8 + ac);
            b4 = *(const float4*)(Bt + (long)(col0+ar)*Dd + k0 + 8 + ac);
        }
#pragma unroll
        for (int k=0;k<8;k++){
            float a[8], b[8];
#pragma unroll
            for (int i=0;i<8;i++) a[i]=As[buf][k][tm+i];
#pragma unroll
            for (int j=0;j<8;j++) b[j]=Bs[buf][k][tn+j];
#pragma unroll
            for (int i=0;i<8;i++)
#pragma unroll
                for (int j=0;j<8;j++) acc[i][j]=fmaf(a[i],b[j],acc[i][j]);
        }
        buf ^= 1;
        if (more) {
            As[buf][ac+0][ar]=a4.x; As[buf][ac+1][ar]=a4.y;
            As[buf][ac+2][ar]=a4.z; As[buf][ac+3][ar]=a4.w;
            Bs[buf][ac+0][ar]=b4.x; Bs[buf][ac+1][ar]=b4.y;
            Bs[buf][ac+2][ar]=b4.z; Bs[buf][ac+3][ar]=b4.w;
        }
        __syncthreads();
    }
#pragma unroll
    for (int i=0;i<8;i++){
        float4 o1 = make_float4(acc[i][0]*0.125f, acc[i][1]*0.125f, acc[i][2]*0.125f, acc[i][3]*0.125f);
        float4 o2 = make_float4(acc[i][4]*0.125f, acc[i][5]*0.125f, acc[i][6]*0.125f, acc[i][7]*0.125f);
        float* p = C + (long)(row0+tm+i)*Ll + col0 + tn;
        *(float4*)(p)   = o1;
        *(float4*)(p+4) = o2;
    }
}

// ============ attn @ v per (b,h): M=1024, N=64, K=1024 =====================
// BM=128, BN=64, BK=8, double-buffered, 8x4 micro, 256 threads.
__global__ __launch_bounds__(256) void attnv64(
    const float* __restrict__ attn, const float* __restrict__ v,
    float* __restrict__ o)
{
    __shared__ float As[2][8][128];
    __shared__ float Bs[2][8][64];
    const int bz = blockIdx.z;
    const float* A = attn + (long)bz*Ll*Ll;
    const float* W = v + (long)(bz>>3)*Ll*Dd + (bz&7)*Ee;
    float* C       = o + (long)(bz>>3)*Ll*Dd + (bz&7)*Ee;
    const int tid = threadIdx.x;
    const int row0 = blockIdx.y * 128;
    const int ar = tid >> 1, ac = (tid & 1) * 4;
    const int br = tid >> 5;              // 0..7
    const int bc = (tid & 31) * 2;        // 0..62
    const int tm = (tid & 15) * 8;
    const int tn = (tid >> 4) * 4;

    float acc[8][4];
#pragma unroll
    for (int i=0;i<8;i++)
#pragma unroll
        for (int j=0;j<4;j++) acc[i][j]=0.f;

    float4 a4 = *(const float4*)(A + (long)(row0+ar)*Ll + ac);
    float2 b2 = *(const float2*)(W + (long)br*Dd + bc);
    As[0][ac+0][ar]=a4.x; As[0][ac+1][ar]=a4.y; As[0][ac+2][ar]=a4.z; As[0][ac+3][ar]=a4.w;
    *(float2*)&Bs[0][br][bc] = b2;
    __syncthreads();

    int buf = 0;
    for (int k0 = 0; k0 < Ll; k0 += 8) {
        const bool more = (k0 + 8) < Ll;
        if (more) {
            a4 = *(const float4*)(A + (long)(row0+ar)*Ll + k0 + 8 + ac);
            b2 = *(const float2*)(W + (long)(k0+8+br)*Dd + bc);
        }
#pragma unroll
        for (int k=0;k<8;k++){
            float a[8], b[4];
#pragma unroll
            for (int i=0;i<8;i++) a[i]=As[buf][k][tm+i];
#pragma unroll
            for (int j=0;j<4;j++) b[j]=Bs[buf][k][tn+j];
#pragma unroll
            for (int i=0;i<8;i++)
#pragma unroll
                for (int j=0;j<4;j++) acc[i][j]=fmaf(a[i],b[j],acc[i][j]);
        }
        buf ^= 1;
        if (more) {
            As[buf][ac+0][ar]=a4.x; As[buf][ac+1][ar]=a4.y;
            As[buf][ac+2][ar]=a4.z; As[buf][ac+3][ar]=a4.w;
            *(float2*)&Bs[buf][br][bc] = b2;
        }
        __syncthreads();
    }
#pragma unroll
    for (int i=0;i<8;i++){
        float4 o1 = make_float4(acc[i][0], acc[i][1], acc[i][2], acc[i][3]);
        *(float4*)(C + (long)(row0+tm+i)*Dd + tn) = o1;
    }
}

// ============ 64x64 GEMM for small N problems (Wx, Wdt) ====================
// act: 0 none, 1 softplus
__global__ __launch_bounds__(256) void gemm64(
    const float* __restrict__ A, int lda,
    const float* __restrict__ W, int ldw,
    const float* __restrict__ bias,
    float* __restrict__ C, int ldc, int K, int act)
{
    __shared__ float As[16][64];
    __shared__ float Ws[16][68];
    const int tid = threadIdx.x;
    const int row0 = blockIdx.y * 64;
    const int col0 = blockIdx.x * 64;
    const int ar = tid >> 2, ac = (tid & 3) * 4;
    const int br = tid >> 4, bc = (tid & 15) * 4;
    const int tm = (tid & 15) * 4, tn = (tid >> 4) * 4;
    float acc[4][4];
#pragma unroll
    for (int i=0;i<4;i++)
#pragma unroll
        for (int j=0;j<4;j++) acc[i][j]=0.f;

    for (int k0 = 0; k0 < K; k0 += 16) {
        float4 a4 = *(const float4*)(A + (long)(row0+ar)*lda + k0 + ac);
        As[ac+0][ar]=a4.x; As[ac+1][ar]=a4.y; As[ac+2][ar]=a4.z; As[ac+3][ar]=a4.w;
        float4 b4 = *(const float4*)(W + (long)(k0+br)*ldw + col0 + bc);
        *(float4*)&Ws[br][bc] = b4;
        __syncthreads();
#pragma unroll
        for (int k=0;k<16;k++){
            float a[4], b[4];
#pragma unroll
            for (int i=0;i<4;i++) a[i]=As[k][tm+i];
#pragma unroll
            for (int j=0;j<4;j++) b[j]=Ws[k][tn+j];
#pragma unroll
            for (int i=0;i<4;i++)
#pragma unroll
                for (int j=0;j<4;j++) acc[i][j]=fmaf(a[i],b[j],acc[i][j]);
        }
        __syncthreads();
    }
#pragma unroll
    for (int j=0;j<4;j++){
        int c = col0 + tn + j;
        float bvv = bias ? bias[c] : 0.f;
#pragma unroll
        for (int i=0;i<4;i++){
            float vv = acc[i][j] + bvv;
            if (act == 1) vv = (vv > 20.f) ? vv : log1pf(__expf(vv));
            C[(long)(row0+tm+i)*ldc + c] = vv;
        }
    }
}

// ---------------- softmax over rows of length 1024 (in place) -------------
__global__ __launch_bounds__(256) void softmax_k(float* __restrict__ a)
{
    const long row = blockIdx.x;
    float* p = a + row * (long)Ll;
    const int tid = threadIdx.x;
    float v[4];
    float m = -1e30f;
#pragma unroll
    for (int i=0;i<4;i++){ v[i] = p[tid + 256*i]; m = fmaxf(m, v[i]); }
#pragma unroll
    for (int off=16; off; off>>=1) m = fmaxf(m, __shfl_xor_sync(0xffffffffu, m, off));
    __shared__ float sm[8], ss[8];
    const int w = tid >> 5, lane = tid & 31;
    if (lane==0) sm[w] = m;
    __syncthreads();
    m = sm[0];
#pragma unroll
    for (int i=1;i<8;i++) m = fmaxf(m, sm[i]);
    float s = 0.f;
#pragma unroll
    for (int i=0;i<4;i++){ v[i] = __expf(v[i]-m); s += v[i]; }
#pragma unroll
    for (int off=16; off; off>>=1) s += __shfl_xor_sync(0xffffffffu, s, off);
    if (lane==0) ss[w] = s;
    __syncthreads();
    s = 0.f;
#pragma unroll
    for (int i=0;i<8;i++) s += ss[i];
    const float inv = 1.f / s;
#pragma unroll
    for (int i=0;i<4;i++) p[tid + 256*i] = v[i] * inv;
}

// ---------------- out = LayerNorm(xa + xb) --------------------------------
__global__ __launch_bounds__(128) void add_ln(
    const float* __restrict__ xa, const float* __restrict__ xb,
    const float* __restrict__ g, const float* __restrict__ bt,
    float* __restrict__ out)
{
    const int row = blockIdx.x, tid = threadIdx.x;
    const float* pa = xa + (long)row*Dd;
    const float* pb = xb + (long)row*Dd;
    float v[4]; float s1=0.f, s2=0.f;
#pragma unroll
    for (int i=0;i<4;i++){ int c = tid + 128*i; v[i] = pa[c] + pb[c]; s1 += v[i]; s2 += v[i]*v[i]; }
#pragma unroll
    for (int off=16; off; off>>=1){
        s1 += __shfl_xor_sync(0xffffffffu, s1, off);
        s2 += __shfl_xor_sync(0xffffffffu, s2, off);
    }
    __shared__ float r1[4], r2[4];
    const int w = tid >> 5, lane = tid & 31;
    if (lane==0){ r1[w]=s1; r2[w]=s2; }
    __syncthreads();
    s1 = r1[0]+r1[1]+r1[2]+r1[3];
    s2 = r2[0]+r2[1]+r2[2]+r2[3];
    const float mean = s1 * (1.f/Dd);
    const float var  = s2 * (1.f/Dd) - mean*mean;
    const float rstd = rsqrtf(var + 1e-5f);
    float* po = out + (long)row*Dd;
#pragma unroll
    for (int i=0;i<4;i++){ int c = tid + 128*i; po[c] = (v[i]-mean)*rstd*g[c] + bt[c]; }
}

// ---------------- depthwise causal conv (K=4) + bias + silu ----------------
__global__ __launch_bounds__(256) void conv_silu_k(
    const float* __restrict__ xz, const float* __restrict__ w,
    const float* __restrict__ cb, float* __restrict__ xc)
{
    const long idx = (long)blockIdx.x*256 + threadIdx.x;  // over Mrows*DINc
    const int d = (int)(idx & (DINc-1));
    const long row = idx >> 10;
    const int l = (int)(row & (Ll-1));
    float acc = cb[d];
#pragma unroll
    for (int j=0;j<4;j++) {
        int ll = l - 3 + j;
        if (ll >= 0)
            acc = fmaf(xz[(row-3+j)*(2*DINc) + d], w[d*4+j], acc);
    }
    xc[idx] = acc / (1.f + __expf(-acc));   // silu
}

// ---------------- selective scan (prefetched), fused epilogue --------------
// block: 128 threads = 8 d-values x 16 states; grid: Bb * DINc/8 = 512
__global__ __launch_bounds__(128) void scan_k(
    const float* __restrict__ dt, const float* __restrict__ xc,
    const float* __restrict__ dbl, const float* __restrict__ xz,
    const float* __restrict__ Alog, const float* __restrict__ Dp,
    float* __restrict__ yact)
{
    const int tid = threadIdx.x;
    const int n  = tid & 15;
    const int dl = tid >> 4;
    const int b  = blockIdx.x >> 7;
    const int d  = (blockIdx.x & 127)*8 + dl;
    const float Aa = -__expf(Alog[d*Nn + n]);
    const float Dv = Dp[d];
    float h = 0.f;
    const long base = (long)b * Ll;

    float dtv = dt[base*DINc + d];
    float xcv = xc[base*DINc + d];
    float Bv  = dbl[base*64 + 32 + n];
    float Cv  = dbl[base*64 + 48 + n];
    float zv  = xz[base*(2*DINc) + DINc + d];

    for (int t = 0; t < Ll; t++) {
        const float dtc = dtv, xcc = xcv, Bc = Bv, Cc = Cv, zc = zv;
        if (t + 1 < Ll) {
            const long r2 = base + t + 1;
            dtv = dt[r2*DINc + d];
            xcv = xc[r2*DINc + d];
            Bv  = dbl[r2*64 + 32 + n];
            Cv  = dbl[r2*64 + 48 + n];
            zv  = xz[r2*(2*DINc) + DINc + d];
        }
        const float dA = __expf(dtc * Aa);
        h = fmaf(h, dA, dtc * xcc * Bc);
        float p = h * Cc;
        p += __shfl_xor_sync(0xffffffffu, p, 8);
        p += __shfl_xor_sync(0xffffffffu, p, 4);
        p += __shfl_xor_sync(0xffffffffu, p, 2);
        p += __shfl_xor_sync(0xffffffffu, p, 1);
        if (n == 0) {
            const float sz = zc / (1.f + __expf(-zc));
            yact[(base+t)*DINc + d] = (p + xcc * Dv) * sz;
        }
    }
}

// ---------------- launch ----------------------------------------------------
extern "C" void kernel_launch(void* const* d_in, const int* in_sizes, int n_in,
                              void* d_out, int out_size)
{
    const float* x    = (const float*)d_in[0];
    const float* Wq   = (const float*)d_in[1];
    const float* bq   = (const float*)d_in[2];
    const float* Wk   = (const float*)d_in[3];
    const float* bk   = (const float*)d_in[4];
    const float* Wv   = (const float*)d_in[5];
    const float* bv   = (const float*)d_in[6];
    const float* Wo   = (const float*)d_in[7];
    const float* bo   = (const float*)d_in[8];
    const float* ln1g = (const float*)d_in[9];
    const float* ln1b = (const float*)d_in[10];
    const float* ln2g = (const float*)d_in[11];
    const float* ln2b = (const float*)d_in[12];
    const float* Win  = (const float*)d_in[13];
    const float* cw   = (const float*)d_in[14];
    const float* cb   = (const float*)d_in[15];
    const float* Wx   = (const float*)d_in[16];
    const float* Wdt  = (const float*)d_in[17];
    const float* bdt  = (const float*)d_in[18];
    const float* Alog = (const float*)d_in[19];
    const float* Dp   = (const float*)d_in[20];
    const float* Wout = (const float*)d_in[21];

    float* out  = (float*)d_out;
    float* attn = out + (size_t)Bb*Ll*Dd;     // output tuple order: (out, attn)

    float *q,*k,*v,*o,*t1,*x1,*xz,*xc,*db,*dtb,*ya,*y;
    cudaGetSymbolAddress((void**)&q,  g_q);
    cudaGetSymbolAddress((void**)&k,  g_k);
    cudaGetSymbolAddress((void**)&v,  g_v);
    cudaGetSymbolAddress((void**)&o,  g_o);
    cudaGetSymbolAddress((void**)&t1, g_t1);
    cudaGetSymbolAddress((void**)&x1, g_x1);
    cudaGetSymbolAddress((void**)&xz, g_xz);
    cudaGetSymbolAddress((void**)&xc, g_xc);
    cudaGetSymbolAddress((void**)&db, g_db);
    cudaGetSymbolAddress((void**)&dtb,g_dt);
    cudaGetSymbolAddress((void**)&ya, g_ya);
    cudaGetSymbolAddress((void**)&y,  g_y);

    // QKV projections (M=4096, N=512, K=512)
    gemm128<<<dim3(Dd/128, Mrows/128), 256>>>(x, Dd, Wq, Dd, bq, q, Dd, Dd);
    gemm128<<<dim3(Dd/128, Mrows/128), 256>>>(x, Dd, Wk, Dd, bk, k, Dd, Dd);
    gemm128<<<dim3(Dd/128, Mrows/128), 256>>>(x, Dd, Wv, Dd, bv, v, Dd, Dd);
    // attention
    scores128<<<dim3(Ll/128, Ll/128, Bb*Hh), 256>>>(q, k, attn);
    softmax_k<<<Bb*Hh*Ll, 256>>>(attn);
    attnv64<<<dim3(1, Ll/128, Bb*Hh), 256>>>(attn, v, o);
    // o @ Wo + bo ; x1 = LN(x + .)
    gemm128<<<dim3(Dd/128, Mrows/128), 256>>>(o, Dd, Wo, Dd, bo, t1, Dd, Dd);
    add_ln<<<Mrows, 128>>>(x, t1, ln1g, ln1b, x1);
    // mamba in-proj (N=2048, K=512)
    gemm128<<<dim3(2*DINc/128, Mrows/128), 256>>>(x1, Dd, Win, 2*DINc, nullptr, xz, 2*DINc, Dd);
    // depthwise conv + silu
    conv_silu_k<<<(Mrows*DINc)/256, 256>>>(xz, cw, cb, xc);
    // dbl = xc @ Wx   (N=64, K=1024)
    gemm64<<<dim3(1, Mrows/64), 256>>>(xc, DINc, Wx, 64, nullptr, db, 64, DINc, 0);
    // dt = softplus(dbl[:, :32] @ Wdt + bdt)  (N=1024, K=32)
    gemm64<<<dim3(DINc/64, Mrows/64), 256>>>(db, 64, Wdt, DINc, bdt, dtb, DINc, Rr, 1);
    // selective scan (+ xc*D, * silu(z))
    scan_k<<<Bb*(DINc/8), 128>>>(dtb, xc, db, xz, Alog, Dp, ya);
    // out-proj (N=512, K=1024) + final LN
    gemm128<<<dim3(Dd/128, Mrows/128), 256>>>(ya, DINc, Wout, Dd, nullptr, y, Dd, DINc);
    add_ln<<<Mrows, 128>>>(x1, y, ln2g, ln2b, out);

    (void)in_sizes; (void)n_in; (void)out_size;
}

// round 10
// speedup vs baseline: 1.6008x; 1.2888x over previous
#include <cuda_runtime.h>
#include <cuda_bf16.h>
#include <math.h>

// ---------------- problem constants ----------------
#define Bb   4
#define Ll   1024
#define Dd   512
#define Hh   8
#define Ee   64
#define DINc 1024
#define Nn   16
#define Rr   32
#define Mrows (Bb*Ll)          // 4096

// ---------------- fp32 scratch ----------------
__device__ float g_q [Mrows*Dd];
__device__ float g_k [Mrows*Dd];
__device__ float g_v [Mrows*Dd];
__device__ float g_o [Mrows*Dd];
__device__ float g_t1[Mrows*Dd];
__device__ float g_x1[Mrows*Dd];
__device__ float g_xz[(size_t)Mrows*2*DINc];
__device__ float g_xc[(size_t)Mrows*DINc];
__device__ float g_db[Mrows*64];
__device__ float g_dt[(size_t)Mrows*DINc];
__device__ float g_ya[(size_t)Mrows*DINc];
__device__ float g_y [Mrows*Dd];

// ---------------- bf16 split scratch (hi/lo) ----------------
__device__ __nv_bfloat16 g_xh [Mrows*Dd],   g_xl [Mrows*Dd];
__device__ __nv_bfloat16 g_oh [Mrows*Dd],   g_ol [Mrows*Dd];
__device__ __nv_bfloat16 g_x1h[Mrows*Dd],   g_x1l[Mrows*Dd];
__device__ __nv_bfloat16 g_yah[(size_t)Mrows*DINc], g_yal[(size_t)Mrows*DINc];
// transposed weights [N][K]
__device__ __nv_bfloat16 g_Wqh[Dd*Dd],  g_Wql[Dd*Dd];
__device__ __nv_bfloat16 g_Wkh[Dd*Dd],  g_Wkl[Dd*Dd];
__device__ __nv_bfloat16 g_Wvh[Dd*Dd],  g_Wvl[Dd*Dd];
__device__ __nv_bfloat16 g_Woh[Dd*Dd],  g_Wol[Dd*Dd];
__device__ __nv_bfloat16 g_Wih[(size_t)Dd*2*DINc], g_Wil[(size_t)Dd*2*DINc];
__device__ __nv_bfloat16 g_Wuh[(size_t)DINc*Dd],   g_Wul[(size_t)DINc*Dd];

// ---------------- helpers ----------------
__device__ __forceinline__ unsigned sptr(const void* p){
    unsigned a;
    asm("{ .reg .u64 t; cvta.to.shared.u64 t, %1; cvt.u32.u64 %0, t; }" : "=r"(a) : "l"(p));
    return a;
}
__device__ __forceinline__ void ldm_x4(unsigned* f, unsigned addr){
    asm volatile("ldmatrix.sync.aligned.m8n8.x4.shared.b16 {%0,%1,%2,%3}, [%4];"
        : "=r"(f[0]), "=r"(f[1]), "=r"(f[2]), "=r"(f[3]) : "r"(addr));
}
__device__ __forceinline__ void mma16816(float* d, const unsigned* a,
                                         unsigned b0, unsigned b1){
    asm volatile(
        "mma.sync.aligned.m16n8k16.row.col.f32.bf16.bf16.f32 "
        "{%0,%1,%2,%3}, {%4,%5,%6,%7}, {%8,%9}, {%0,%1,%2,%3};"
        : "+f"(d[0]), "+f"(d[1]), "+f"(d[2]), "+f"(d[3])
        : "r"(a[0]), "r"(a[1]), "r"(a[2]), "r"(a[3]), "r"(b0), "r"(b1));
}

// ================= bf16 3x-split tensor-core GEMM ==========================
// C[M,N] = (Ah+Al)[M,K] @ (Bh+Bl)^T, B stored [N][K]. BM=BN=128, BK=32.
// 256 threads = 8 warps, warp tile 32x64 (n processed in two halves of 32).
__global__ __launch_bounds__(256) void gemm_mma(
    const __nv_bfloat16* __restrict__ Ah, const __nv_bfloat16* __restrict__ Al,
    const __nv_bfloat16* __restrict__ Bh, const __nv_bfloat16* __restrict__ Bl,
    const float* __restrict__ bias, float* __restrict__ C, int ldc, int K)
{
    __shared__ __nv_bfloat16 sAh[128][40], sAl[128][40];
    __shared__ __nv_bfloat16 sBh[128][40], sBl[128][40];
    const int tid = threadIdx.x;
    const int wid = tid >> 5, lane = tid & 31;
    const int row0 = blockIdx.y * 128, col0 = blockIdx.x * 128;
    const int wm = (wid & 3) * 32;          // warp m offset
    const int wn = (wid >> 2) * 64;         // warp n offset

    float acc[2][8][4];
#pragma unroll
    for (int i=0;i<2;i++)
#pragma unroll
        for (int j=0;j<8;j++)
#pragma unroll
            for (int t=0;t<4;t++) acc[i][j][t]=0.f;

    const int lr = lane & 15, lh = (lane >> 4) * 8;   // ldmatrix row / k-half

    for (int k0 = 0; k0 < K; k0 += 32) {
        // ---- stage 4 tiles (128x32 bf16 each) ----
#pragma unroll
        for (int s = 0; s < 2; s++) {
            const int idx = s * 256 + tid;
            const int r = idx >> 2, c = (idx & 3) * 8;
            const long goff = (long)(row0 + r) * K + k0 + c;
            const long hoff = (long)(col0 + r) * K + k0 + c;
            *(uint4*)&sAh[r][c] = *(const uint4*)(Ah + goff);
            *(uint4*)&sAl[r][c] = *(const uint4*)(Al + goff);
            *(uint4*)&sBh[r][c] = *(const uint4*)(Bh + hoff);
            *(uint4*)&sBl[r][c] = *(const uint4*)(Bl + hoff);
        }
        __syncthreads();

#pragma unroll
        for (int kk = 0; kk < 32; kk += 16) {
            unsigned ah[2][4], al[2][4];
#pragma unroll
            for (int mi = 0; mi < 2; mi++) {
                ldm_x4(ah[mi], sptr(&sAh[wm + mi*16 + lr][kk + lh]));
                ldm_x4(al[mi], sptr(&sAl[wm + mi*16 + lr][kk + lh]));
            }
            // process 64-wide n in two halves of 32 (2 ldmatrix.x4 pairs each)
#pragma unroll
            for (int half = 0; half < 2; half++) {
                unsigned bh[4][2], bl[4][2];
#pragma unroll
                for (int p = 0; p < 2; p++) {
                    unsigned f[4];
                    ldm_x4(f, sptr(&sBh[wn + half*32 + p*16 + lr][kk + lh]));
                    bh[2*p+0][0]=f[0]; bh[2*p+0][1]=f[2];
                    bh[2*p+1][0]=f[1]; bh[2*p+1][1]=f[3];
                    ldm_x4(f, sptr(&sBl[wn + half*32 + p*16 + lr][kk + lh]));
                    bl[2*p+0][0]=f[0]; bl[2*p+0][1]=f[2];
                    bl[2*p+1][0]=f[1]; bl[2*p+1][1]=f[3];
                }
#pragma unroll
                for (int mi = 0; mi < 2; mi++)
#pragma unroll
                    for (int nj = 0; nj < 4; nj++) {
                        float* a = acc[mi][half*4 + nj];
                        mma16816(a, ah[mi], bh[nj][0], bh[nj][1]);
                        mma16816(a, ah[mi], bl[nj][0], bl[nj][1]);
                        mma16816(a, al[mi], bh[nj][0], bh[nj][1]);
                    }
            }
        }
        __syncthreads();
    }

    // ---- epilogue ----
#pragma unroll
    for (int mi = 0; mi < 2; mi++) {
        const int r = row0 + wm + mi*16 + (lane >> 2);
#pragma unroll
        for (int ni = 0; ni < 8; ni++) {
            const int c = col0 + wn + (ni>>2)*32 + (ni&3)*8 + (lane & 3)*2;
            float b0 = 0.f, b1 = 0.f;
            if (bias) { b0 = bias[c]; b1 = bias[c+1]; }
            *(float2*)(C + (long)r*ldc + c) =
                make_float2(acc[mi][ni][0]+b0, acc[mi][ni][1]+b1);
            *(float2*)(C + (long)(r+8)*ldc + c) =
                make_float2(acc[mi][ni][2]+b0, acc[mi][ni][3]+b1);
        }
    }
}

// ================= split conversions =======================================
__global__ __launch_bounds__(256) void split_act(
    const float* __restrict__ x, __nv_bfloat16* __restrict__ h,
    __nv_bfloat16* __restrict__ l)
{
    const int i = blockIdx.x * 256 + threadIdx.x;
    const float v = x[i];
    const __nv_bfloat16 hi = __float2bfloat16(v);
    h[i] = hi;
    l[i] = __float2bfloat16(v - __bfloat162float(hi));
}

// W [K][N] fp32 -> Wt hi/lo bf16 [N][K]
__global__ __launch_bounds__(256) void split_wt(
    const float* __restrict__ W, int Kdim, int Ndim,
    __nv_bfloat16* __restrict__ h, __nv_bfloat16* __restrict__ l)
{
    __shared__ float t[32][33];
    const int tx = threadIdx.x, ty = threadIdx.y;     // (32, 8)
    const int n0 = blockIdx.x * 32, k0 = blockIdx.y * 32;
#pragma unroll
    for (int j = 0; j < 4; j++)
        t[ty + 8 * j][tx] = W[(long)(k0 + ty + 8 * j) * Ndim + n0 + tx];
    __syncthreads();
#pragma unroll
    for (int j = 0; j < 4; j++) {
        const float v = t[tx][ty + 8 * j];
        const __nv_bfloat16 hi = __float2bfloat16(v);
        const long oidx = (long)(n0 + ty + 8 * j) * Kdim + k0 + tx;
        h[oidx] = hi;
        l[oidx] = __float2bfloat16(v - __bfloat162float(hi));
    }
}

// ============ scores: S = q @ k^T * 0.125, per (b,h) (SIMT fp32) ===========
__global__ __launch_bounds__(256) void scores128(
    const float* __restrict__ q, const float* __restrict__ kk,
    float* __restrict__ attn)
{
    __shared__ float As[2][8][128];
    __shared__ float Bs[2][8][128];
    const int bz = blockIdx.z;
    const float* A  = q  + (long)(bz>>3)*Ll*Dd + (bz&7)*Ee;
    const float* Bt = kk + (long)(bz>>3)*Ll*Dd + (bz&7)*Ee;
    float* C = attn + (long)bz*Ll*Ll;
    const int tid = threadIdx.x;
    const int row0 = blockIdx.y * 128;
    const int col0 = blockIdx.x * 128;
    const int ar = tid >> 1, ac = (tid & 1) * 4;
    const int tm = (tid & 15) * 8;
    const int tn = (tid >> 4) * 8;

    float acc[8][8];
#pragma unroll
    for (int i=0;i<8;i++)
#pragma unroll
        for (int j=0;j<8;j++) acc[i][j]=0.f;

    float4 a4 = *(const float4*)(A  + (long)(row0+ar)*Dd + ac);
    float4 b4 = *(const float4*)(Bt + (long)(col0+ar)*Dd + ac);
    As[0][ac+0][ar]=a4.x; As[0][ac+1][ar]=a4.y; As[0][ac+2][ar]=a4.z; As[0][ac+3][ar]=a4.w;
    Bs[0][ac+0][ar]=b4.x; Bs[0][ac+1][ar]=b4.y; Bs[0][ac+2][ar]=b4.z; Bs[0][ac+3][ar]=b4.w;
    __syncthreads();

    int buf = 0;
    for (int k0 = 0; k0 < Ee; k0 += 8) {
        const bool more = (k0 + 8) < Ee;
        if (more) {
            a4 = *(const float4*)(A  + (long)(row0+ar)*Dd + k0 + 8 + ac);
            b4 = *(const float4*)(Bt + (long)(col0+ar)*Dd + k0 + 8 + ac);
        }
#pragma unroll
        for (int k=0;k<8;k++){
            float a[8], b[8];
#pragma unroll
            for (int i=0;i<8;i++) a[i]=As[buf][k][tm+i];
#pragma unroll
            for (int j=0;j<8;j++) b[j]=Bs[buf][k][tn+j];
#pragma unroll
            for (int i=0;i<8;i++)
#pragma unroll
                for (int j=0;j<8;j++) acc[i][j]=fmaf(a[i],b[j],acc[i][j]);
        }
        buf ^= 1;
        if (more) {
            As[buf][ac+0][ar]=a4.x; As[buf][ac+1][ar]=a4.y;
            As[buf][ac+2][ar]=a4.z; As[buf][ac+3][ar]=a4.w;
            Bs[buf][ac+0][ar]=b4.x; Bs[buf][ac+1][ar]=b4.y;
            Bs[buf][ac+2][ar]=b4.z; Bs[buf][ac+3][ar]=b4.w;
        }
        __syncthreads();
    }
#pragma unroll
    for (int i=0;i<8;i++){
        float4 o1 = make_float4(acc[i][0]*0.125f, acc[i][1]*0.125f, acc[i][2]*0.125f, acc[i][3]*0.125f);
        float4 o2 = make_float4(acc[i][4]*0.125f, acc[i][5]*0.125f, acc[i][6]*0.125f, acc[i][7]*0.125f);
        float* p = C + (long)(row0+tm+i)*Ll + col0 + tn;
        *(float4*)(p)   = o1;
        *(float4*)(p+4) = o2;
    }
}

// ============ attn @ v per (b,h) (SIMT fp32) ===============================
__global__ __launch_bounds__(256) void attnv64(
    const float* __restrict__ attn, const float* __restrict__ v,
    float* __restrict__ o)
{
    __shared__ float As[2][8][128];
    __shared__ float Bs[2][8][64];
    const int bz = blockIdx.z;
    const float* A = attn + (long)bz*Ll*Ll;
    const float* W = v + (long)(bz>>3)*Ll*Dd + (bz&7)*Ee;
    float* C       = o + (long)(bz>>3)*Ll*Dd + (bz&7)*Ee;
    const int tid = threadIdx.x;
    const int row0 = blockIdx.y * 128;
    const int ar = tid >> 1, ac = (tid & 1) * 4;
    const int br = tid >> 5;
    const int bc = (tid & 31) * 2;
    const int tm = (tid & 15) * 8;
    const int tn = (tid >> 4) * 4;

    float acc[8][4];
#pragma unroll
    for (int i=0;i<8;i++)
#pragma unroll
        for (int j=0;j<4;j++) acc[i][j]=0.f;

    float4 a4 = *(const float4*)(A + (long)(row0+ar)*Ll + ac);
    float2 b2 = *(const float2*)(W + (long)br*Dd + bc);
    As[0][ac+0][ar]=a4.x; As[0][ac+1][ar]=a4.y; As[0][ac+2][ar]=a4.z; As[0][ac+3][ar]=a4.w;
    *(float2*)&Bs[0][br][bc] = b2;
    __syncthreads();

    int buf = 0;
    for (int k0 = 0; k0 < Ll; k0 += 8) {
        const bool more = (k0 + 8) < Ll;
        if (more) {
            a4 = *(const float4*)(A + (long)(row0+ar)*Ll + k0 + 8 + ac);
            b2 = *(const float2*)(W + (long)(k0+8+br)*Dd + bc);
        }
#pragma unroll
        for (int k=0;k<8;k++){
            float a[8], b[4];
#pragma unroll
            for (int i=0;i<8;i++) a[i]=As[buf][k][tm+i];
#pragma unroll
            for (int j=0;j<4;j++) b[j]=Bs[buf][k][tn+j];
#pragma unroll
            for (int i=0;i<8;i++)
#pragma unroll
                for (int j=0;j<4;j++) acc[i][j]=fmaf(a[i],b[j],acc[i][j]);
        }
        buf ^= 1;
        if (more) {
            As[buf][ac+0][ar]=a4.x; As[buf][ac+1][ar]=a4.y;
            As[buf][ac+2][ar]=a4.z; As[buf][ac+3][ar]=a4.w;
            *(float2*)&Bs[buf][br][bc] = b2;
        }
        __syncthreads();
    }
#pragma unroll
    for (int i=0;i<8;i++){
        float4 o1 = make_float4(acc[i][0], acc[i][1], acc[i][2], acc[i][3]);
        *(float4*)(C + (long)(row0+tm+i)*Dd + tn) = o1;
    }
}

// ============ 64x64 GEMM for small N problems (Wx, Wdt) ====================
__global__ __launch_bounds__(256) void gemm64(
    const float* __restrict__ A, int lda,
    const float* __restrict__ W, int ldw,
    const float* __restrict__ bias,
    float* __restrict__ C, int ldc, int K, int act)
{
    __shared__ float As[16][64];
    __shared__ float Ws[16][68];
    const int tid = threadIdx.x;
    const int row0 = blockIdx.y * 64;
    const int col0 = blockIdx.x * 64;
    const int ar = tid >> 2, ac = (tid & 3) * 4;
    const int br = tid >> 4, bc = (tid & 15) * 4;
    const int tm = (tid & 15) * 4, tn = (tid >> 4) * 4;
    float acc[4][4];
#pragma unroll
    for (int i=0;i<4;i++)
#pragma unroll
        for (int j=0;j<4;j++) acc[i][j]=0.f;

    for (int k0 = 0; k0 < K; k0 += 16) {
        float4 a4 = *(const float4*)(A + (long)(row0+ar)*lda + k0 + ac);
        As[ac+0][ar]=a4.x; As[ac+1][ar]=a4.y; As[ac+2][ar]=a4.z; As[ac+3][ar]=a4.w;
        float4 b4 = *(const float4*)(W + (long)(k0+br)*ldw + col0 + bc);
        *(float4*)&Ws[br][bc] = b4;
        __syncthreads();
#pragma unroll
        for (int k=0;k<16;k++){
            float a[4], b[4];
#pragma unroll
            for (int i=0;i<4;i++) a[i]=As[k][tm+i];
#pragma unroll
            for (int j=0;j<4;j++) b[j]=Ws[k][tn+j];
#pragma unroll
            for (int i=0;i<4;i++)
#pragma unroll
                for (int j=0;j<4;j++) acc[i][j]=fmaf(a[i],b[j],acc[i][j]);
        }
        __syncthreads();
    }
#pragma unroll
    for (int j=0;j<4;j++){
        int c = col0 + tn + j;
        float bvv = bias ? bias[c] : 0.f;
#pragma unroll
        for (int i=0;i<4;i++){
            float vv = acc[i][j] + bvv;
            if (act == 1) vv = (vv > 20.f) ? vv : log1pf(__expf(vv));
            C[(long)(row0+tm+i)*ldc + c] = vv;
        }
    }
}

// ---------------- softmax over rows of length 1024 (in place) -------------
__global__ __launch_bounds__(256) void softmax_k(float* __restrict__ a)
{
    const long row = blockIdx.x;
    float* p = a + row * (long)Ll;
    const int tid = threadIdx.x;
    float v[4];
    float m = -1e30f;
#pragma unroll
    for (int i=0;i<4;i++){ v[i] = p[tid + 256*i]; m = fmaxf(m, v[i]); }
#pragma unroll
    for (int off=16; off; off>>=1) m = fmaxf(m, __shfl_xor_sync(0xffffffffu, m, off));
    __shared__ float sm[8], ss[8];
    const int w = tid >> 5, lane = tid & 31;
    if (lane==0) sm[w] = m;
    __syncthreads();
    m = sm[0];
#pragma unroll
    for (int i=1;i<8;i++) m = fmaxf(m, sm[i]);
    float s = 0.f;
#pragma unroll
    for (int i=0;i<4;i++){ v[i] = __expf(v[i]-m); s += v[i]; }
#pragma unroll
    for (int off=16; off; off>>=1) s += __shfl_xor_sync(0xffffffffu, s, off);
    if (lane==0) ss[w] = s;
    __syncthreads();
    s = 0.f;
#pragma unroll
    for (int i=0;i<8;i++) s += ss[i];
    const float inv = 1.f / s;
#pragma unroll
    for (int i=0;i<4;i++) p[tid + 256*i] = v[i] * inv;
}

// ---------------- out = LayerNorm(xa + xb) --------------------------------
__global__ __launch_bounds__(128) void add_ln(
    const float* __restrict__ xa, const float* __restrict__ xb,
    const float* __restrict__ g, const float* __restrict__ bt,
    float* __restrict__ out)
{
    const int row = blockIdx.x, tid = threadIdx.x;
    const float* pa = xa + (long)row*Dd;
    const float* pb = xb + (long)row*Dd;
    float v[4]; float s1=0.f, s2=0.f;
#pragma unroll
    for (int i=0;i<4;i++){ int c = tid + 128*i; v[i] = pa[c] + pb[c]; s1 += v[i]; s2 += v[i]*v[i]; }
#pragma unroll
    for (int off=16; off; off>>=1){
        s1 += __shfl_xor_sync(0xffffffffu, s1, off);
        s2 += __shfl_xor_sync(0xffffffffu, s2, off);
    }
    __shared__ float r1[4], r2[4];
    const int w = tid >> 5, lane = tid & 31;
    if (lane==0){ r1[w]=s1; r2[w]=s2; }
    __syncthreads();
    s1 = r1[0]+r1[1]+r1[2]+r1[3];
    s2 = r2[0]+r2[1]+r2[2]+r2[3];
    const float mean = s1 * (1.f/Dd);
    const float var  = s2 * (1.f/Dd) - mean*mean;
    const float rstd = rsqrtf(var + 1e-5f);
    float* po = out + (long)row*Dd;
#pragma unroll
    for (int i=0;i<4;i++){ int c = tid + 128*i; po[c] = (v[i]-mean)*rstd*g[c] + bt[c]; }
}

// ---------------- depthwise causal conv (K=4) + bias + silu ----------------
__global__ __launch_bounds__(256) void conv_silu_k(
    const float* __restrict__ xz, const float* __restrict__ w,
    const float* __restrict__ cb, float* __restrict__ xc)
{
    const long idx = (long)blockIdx.x*256 + threadIdx.x;
    const int d = (int)(idx & (DINc-1));
    const long row = idx >> 10;
    const int l = (int)(row & (Ll-1));
    float acc = cb[d];
#pragma unroll
    for (int j=0;j<4;j++) {
        int ll = l - 3 + j;
        if (ll >= 0)
            acc = fmaf(xz[(row-3+j)*(2*DINc) + d], w[d*4+j], acc);
    }
    xc[idx] = acc / (1.f + __expf(-acc));
}

// ---------------- selective scan (prefetched), fused epilogue --------------
__global__ __launch_bounds__(128) void scan_k(
    const float* __restrict__ dt, const float* __restrict__ xc,
    const float* __restrict__ dbl, const float* __restrict__ xz,
    const float* __restrict__ Alog, const float* __restrict__ Dp,
    float* __restrict__ yact)
{
    const int tid = threadIdx.x;
    const int n  = tid & 15;
    const int dl = tid >> 4;
    const int b  = blockIdx.x >> 7;
    const int d  = (blockIdx.x & 127)*8 + dl;
    const float Aa = -__expf(Alog[d*Nn + n]);
    const float Dv = Dp[d];
    float h = 0.f;
    const long base = (long)b * Ll;

    float dtv = dt[base*DINc + d];
    float xcv = xc[base*DINc + d];
    float Bv  = dbl[base*64 + 32 + n];
    float Cv  = dbl[base*64 + 48 + n];
    float zv  = xz[base*(2*DINc) + DINc + d];

    for (int t = 0; t < Ll; t++) {
        const float dtc = dtv, xcc = xcv, Bc = Bv, Cc = Cv, zc = zv;
        if (t + 1 < Ll) {
            const long r2 = base + t + 1;
            dtv = dt[r2*DINc + d];
            xcv = xc[r2*DINc + d];
            Bv  = dbl[r2*64 + 32 + n];
            Cv  = dbl[r2*64 + 48 + n];
            zv  = xz[r2*(2*DINc) + DINc + d];
        }
        const float dA = __expf(dtc * Aa);
        h = fmaf(h, dA, dtc * xcc * Bc);
        float p = h * Cc;
        p += __shfl_xor_sync(0xffffffffu, p, 8);
        p += __shfl_xor_sync(0xffffffffu, p, 4);
        p += __shfl_xor_sync(0xffffffffu, p, 2);
        p += __shfl_xor_sync(0xffffffffu, p, 1);
        if (n == 0) {
            const float sz = zc / (1.f + __expf(-zc));
            yact[(base+t)*DINc + d] = (p + xcc * Dv) * sz;
        }
    }
}

// ---------------- launch ----------------------------------------------------
extern "C" void kernel_launch(void* const* d_in, const int* in_sizes, int n_in,
                              void* d_out, int out_size)
{
    const float* x    = (const float*)d_in[0];
    const float* Wq   = (const float*)d_in[1];
    const float* bq   = (const float*)d_in[2];
    const float* Wk   = (const float*)d_in[3];
    const float* bk   = (const float*)d_in[4];
    const float* Wv   = (const float*)d_in[5];
    const float* bv   = (const float*)d_in[6];
    const float* Wo   = (const float*)d_in[7];
    const float* bo   = (const float*)d_in[8];
    const float* ln1g = (const float*)d_in[9];
    const float* ln1b = (const float*)d_in[10];
    const float* ln2g = (const float*)d_in[11];
    const float* ln2b = (const float*)d_in[12];
    const float* Win  = (const float*)d_in[13];
    const float* cw   = (const float*)d_in[14];
    const float* cb   = (const float*)d_in[15];
    const float* Wx   = (const float*)d_in[16];
    const float* Wdt  = (const float*)d_in[17];
    const float* bdt  = (const float*)d_in[18];
    const float* Alog = (const float*)d_in[19];
    const float* Dp   = (const float*)d_in[20];
    const float* Wout = (const float*)d_in[21];

    float* out  = (float*)d_out;
    float* attn = out + (size_t)Bb*Ll*Dd;

    float *q,*k,*v,*o,*t1,*x1,*xz,*xc,*db,*dtb,*ya,*y;
    cudaGetSymbolAddress((void**)&q,  g_q);
    cudaGetSymbolAddress((void**)&k,  g_k);
    cudaGetSymbolAddress((void**)&v,  g_v);
    cudaGetSymbolAddress((void**)&o,  g_o);
    cudaGetSymbolAddress((void**)&t1, g_t1);
    cudaGetSymbolAddress((void**)&x1, g_x1);
    cudaGetSymbolAddress((void**)&xz, g_xz);
    cudaGetSymbolAddress((void**)&xc, g_xc);
    cudaGetSymbolAddress((void**)&db, g_db);
    cudaGetSymbolAddress((void**)&dtb,g_dt);
    cudaGetSymbolAddress((void**)&ya, g_ya);
    cudaGetSymbolAddress((void**)&y,  g_y);

    __nv_bfloat16 *xh,*xl,*oh,*ol,*x1h,*x1l,*yah,*yal;
    __nv_bfloat16 *Wqh,*Wql,*Wkh,*Wkl,*Wvh,*Wvl,*Woh,*Wol,*Wih,*Wil,*Wuh,*Wul;
    cudaGetSymbolAddress((void**)&xh,  g_xh);  cudaGetSymbolAddress((void**)&xl,  g_xl);
    cudaGetSymbolAddress((void**)&oh,  g_oh);  cudaGetSymbolAddress((void**)&ol,  g_ol);
    cudaGetSymbolAddress((void**)&x1h, g_x1h); cudaGetSymbolAddress((void**)&x1l, g_x1l);
    cudaGetSymbolAddress((void**)&yah, g_yah); cudaGetSymbolAddress((void**)&yal, g_yal);
    cudaGetSymbolAddress((void**)&Wqh, g_Wqh); cudaGetSymbolAddress((void**)&Wql, g_Wql);
    cudaGetSymbolAddress((void**)&Wkh, g_Wkh); cudaGetSymbolAddress((void**)&Wkl, g_Wkl);
    cudaGetSymbolAddress((void**)&Wvh, g_Wvh); cudaGetSymbolAddress((void**)&Wvl, g_Wvl);
    cudaGetSymbolAddress((void**)&Woh, g_Woh); cudaGetSymbolAddress((void**)&Wol, g_Wol);
    cudaGetSymbolAddress((void**)&Wih, g_Wih); cudaGetSymbolAddress((void**)&Wil, g_Wil);
    cudaGetSymbolAddress((void**)&Wuh, g_Wuh); cudaGetSymbolAddress((void**)&Wul, g_Wul);

    // weight conversions (transpose + hi/lo split)
    split_wt<<<dim3(Dd/32, Dd/32), dim3(32,8)>>>(Wq, Dd, Dd, Wqh, Wql);
    split_wt<<<dim3(Dd/32, Dd/32), dim3(32,8)>>>(Wk, Dd, Dd, Wkh, Wkl);
    split_wt<<<dim3(Dd/32, Dd/32), dim3(32,8)>>>(Wv, Dd, Dd, Wvh, Wvl);
    split_wt<<<dim3(Dd/32, Dd/32), dim3(32,8)>>>(Wo, Dd, Dd, Woh, Wol);
    split_wt<<<dim3(2*DINc/32, Dd/32), dim3(32,8)>>>(Win, Dd, 2*DINc, Wih, Wil);
    split_wt<<<dim3(Dd/32, DINc/32), dim3(32,8)>>>(Wout, DINc, Dd, Wuh, Wul);

    // x split + QKV (tensor cores)
    split_act<<<(Mrows*Dd)/256, 256>>>(x, xh, xl);
    gemm_mma<<<dim3(Dd/128, Mrows/128), 256>>>(xh, xl, Wqh, Wql, bq, q, Dd, Dd);
    gemm_mma<<<dim3(Dd/128, Mrows/128), 256>>>(xh, xl, Wkh, Wkl, bk, k, Dd, Dd);
    gemm_mma<<<dim3(Dd/128, Mrows/128), 256>>>(xh, xl, Wvh, Wvl, bv, v, Dd, Dd);

    // attention (SIMT fp32 — attn is an output, keep full precision)
    scores128<<<dim3(Ll/128, Ll/128, Bb*Hh), 256>>>(q, k, attn);
    softmax_k<<<Bb*Hh*Ll, 256>>>(attn);
    attnv64<<<dim3(1, Ll/128, Bb*Hh), 256>>>(attn, v, o);

    // o @ Wo + bo (tensor cores) ; x1 = LN(x + .)
    split_act<<<(Mrows*Dd)/256, 256>>>(o, oh, ol);
    gemm_mma<<<dim3(Dd/128, Mrows/128), 256>>>(oh, ol, Woh, Wol, bo, t1, Dd, Dd);
    add_ln<<<Mrows, 128>>>(x, t1, ln1g, ln1b, x1);

    // mamba in-proj (tensor cores, N=2048)
    split_act<<<(Mrows*Dd)/256, 256>>>(x1, x1h, x1l);
    gemm_mma<<<dim3(2*DINc/128, Mrows/128), 256>>>(x1h, x1l, Wih, Wil, nullptr, xz, 2*DINc, Dd);

    // conv + silu
    conv_silu_k<<<(Mrows*DINc)/256, 256>>>(xz, cw, cb, xc);
    // dbl = xc @ Wx   (N=64, K=1024)
    gemm64<<<dim3(1, Mrows/64), 256>>>(xc, DINc, Wx, 64, nullptr, db, 64, DINc, 0);
    // dt = softplus(dbl[:, :32] @ Wdt + bdt)
    gemm64<<<dim3(DINc/64, Mrows/64), 256>>>(db, 64, Wdt, DINc, bdt, dtb, DINc, Rr, 1);
    // selective scan
    scan_k<<<Bb*(DINc/8), 128>>>(dtb, xc, db, xz, Alog, Dp, ya);

    // out-proj (tensor cores, K=1024) + final LN
    split_act<<<((size_t)Mrows*DINc)/256, 256>>>(ya, yah, yal);
    gemm_mma<<<dim3(Dd/128, Mrows/128), 256>>>(yah, yal, Wuh, Wul, nullptr, y, Dd, DINc);
    add_ln<<<Mrows, 128>>>(x1, y, ln2g, ln2b, out);

    (void)in_sizes; (void)n_in; (void)out_size;
}

// round 11
// speedup vs baseline: 1.8709x; 1.1688x over previous
#include <cuda_runtime.h>
#include <cuda_bf16.h>
#include <math.h>

// ---------------- problem constants ----------------
#define Bb   4
#define Ll   1024
#define Dd   512
#define Hh   8
#define Ee   64
#define DINc 1024
#define Nn   16
#define Rr   32
#define Mrows (Bb*Ll)          // 4096

// ---------------- fp32 scratch ----------------
__device__ float g_t1[Mrows*Dd];
__device__ float g_x1[Mrows*Dd];
__device__ float g_xz[(size_t)Mrows*2*DINc];
__device__ float g_xc[(size_t)Mrows*DINc];
__device__ float g_db[Mrows*64];
__device__ float g_dt[(size_t)Mrows*DINc];
__device__ float g_y [Mrows*Dd];

// ---------------- bf16 pair scratch (hi/lo) ----------------
__device__ __nv_bfloat16 g_xh [Mrows*Dd],   g_xl [Mrows*Dd];
__device__ __nv_bfloat16 g_qh [Mrows*Dd],   g_ql [Mrows*Dd];
__device__ __nv_bfloat16 g_kh [Mrows*Dd],   g_kl [Mrows*Dd];
__device__ __nv_bfloat16 g_vh [Mrows*Dd],   g_vl [Mrows*Dd];
__device__ __nv_bfloat16 g_vth[(size_t)Bb*Hh*Ee*Ll], g_vtl[(size_t)Bb*Hh*Ee*Ll];
__device__ __nv_bfloat16 g_ah [(size_t)Bb*Hh*Ll*Ll], g_al [(size_t)Bb*Hh*Ll*Ll];
__device__ __nv_bfloat16 g_oh [Mrows*Dd],   g_ol [Mrows*Dd];
__device__ __nv_bfloat16 g_x1h[Mrows*Dd],   g_x1l[Mrows*Dd];
__device__ __nv_bfloat16 g_yah[(size_t)Mrows*DINc], g_yal[(size_t)Mrows*DINc];
// transposed weights [N][K]
__device__ __nv_bfloat16 g_Wqh[Dd*Dd],  g_Wql[Dd*Dd];
__device__ __nv_bfloat16 g_Wkh[Dd*Dd],  g_Wkl[Dd*Dd];
__device__ __nv_bfloat16 g_Wvh[Dd*Dd],  g_Wvl[Dd*Dd];
__device__ __nv_bfloat16 g_Woh[Dd*Dd],  g_Wol[Dd*Dd];
__device__ __nv_bfloat16 g_Wih[(size_t)Dd*2*DINc], g_Wil[(size_t)Dd*2*DINc];
__device__ __nv_bfloat16 g_Wuh[(size_t)DINc*Dd],   g_Wul[(size_t)DINc*Dd];

// ---------------- helpers ----------------
__device__ __forceinline__ unsigned sptr(const void* p){
    unsigned a;
    asm("{ .reg .u64 t; cvta.to.shared.u64 t, %1; cvt.u32.u64 %0, t; }" : "=r"(a) : "l"(p));
    return a;
}
__device__ __forceinline__ void ldm_x4(unsigned* f, unsigned addr){
    asm volatile("ldmatrix.sync.aligned.m8n8.x4.shared.b16 {%0,%1,%2,%3}, [%4];"
        : "=r"(f[0]), "=r"(f[1]), "=r"(f[2]), "=r"(f[3]) : "r"(addr));
}
__device__ __forceinline__ void mma16816(float* d, const unsigned* a,
                                         unsigned b0, unsigned b1){
    asm volatile(
        "mma.sync.aligned.m16n8k16.row.col.f32.bf16.bf16.f32 "
        "{%0,%1,%2,%3}, {%4,%5,%6,%7}, {%8,%9}, {%0,%1,%2,%3};"
        : "+f"(d[0]), "+f"(d[1]), "+f"(d[2]), "+f"(d[3])
        : "r"(a[0]), "r"(a[1]), "r"(a[2]), "r"(a[3]), "r"(b0), "r"(b1));
}
__device__ __forceinline__ void split2(float v, __nv_bfloat16& h, __nv_bfloat16& l){
    h = __float2bfloat16(v);
    l = __float2bfloat16(v - __bfloat162float(h));
}

// ================= unified 3x-split tensor-core GEMM =======================
// C[M,N] = (Ah+Al)[M,K] @ (Bh+Bl)^T, B stored [N][K]. BM=BN=128, BK=32.
// Output: if Ch != nullptr, write bf16 hi/lo pair; else fp32 to Cf.
__global__ __launch_bounds__(256) void gemm_mma(
    const __nv_bfloat16* __restrict__ Ah, const __nv_bfloat16* __restrict__ Al,
    const __nv_bfloat16* __restrict__ Bh, const __nv_bfloat16* __restrict__ Bl,
    const float* __restrict__ bias,
    float* __restrict__ Cf, __nv_bfloat16* __restrict__ Ch,
    __nv_bfloat16* __restrict__ Cl, int ldc, int K)
{
    __shared__ __nv_bfloat16 sAh[128][40], sAl[128][40];
    __shared__ __nv_bfloat16 sBh[128][40], sBl[128][40];
    const int tid = threadIdx.x;
    const int wid = tid >> 5, lane = tid & 31;
    const int row0 = blockIdx.y * 128, col0 = blockIdx.x * 128;
    const int wm = (wid & 3) * 32;
    const int wn = (wid >> 2) * 64;

    float acc[2][8][4];
#pragma unroll
    for (int i=0;i<2;i++)
#pragma unroll
        for (int j=0;j<8;j++)
#pragma unroll
            for (int t=0;t<4;t++) acc[i][j][t]=0.f;

    const int lr = lane & 15, lh = (lane >> 4) * 8;

    for (int k0 = 0; k0 < K; k0 += 32) {
#pragma unroll
        for (int s = 0; s < 2; s++) {
            const int idx = s * 256 + tid;
            const int r = idx >> 2, c = (idx & 3) * 8;
            const long goff = (long)(row0 + r) * K + k0 + c;
            const long hoff = (long)(col0 + r) * K + k0 + c;
            *(uint4*)&sAh[r][c] = *(const uint4*)(Ah + goff);
            *(uint4*)&sAl[r][c] = *(const uint4*)(Al + goff);
            *(uint4*)&sBh[r][c] = *(const uint4*)(Bh + hoff);
            *(uint4*)&sBl[r][c] = *(const uint4*)(Bl + hoff);
        }
        __syncthreads();

#pragma unroll
        for (int kk = 0; kk < 32; kk += 16) {
            unsigned ahf[2][4], alf[2][4];
#pragma unroll
            for (int mi = 0; mi < 2; mi++) {
                ldm_x4(ahf[mi], sptr(&sAh[wm + mi*16 + lr][kk + lh]));
                ldm_x4(alf[mi], sptr(&sAl[wm + mi*16 + lr][kk + lh]));
            }
#pragma unroll
            for (int half = 0; half < 2; half++) {
                unsigned bh[4][2], bl[4][2];
#pragma unroll
                for (int p = 0; p < 2; p++) {
                    unsigned f[4];
                    ldm_x4(f, sptr(&sBh[wn + half*32 + p*16 + lr][kk + lh]));
                    bh[2*p+0][0]=f[0]; bh[2*p+0][1]=f[2];
                    bh[2*p+1][0]=f[1]; bh[2*p+1][1]=f[3];
                    ldm_x4(f, sptr(&sBl[wn + half*32 + p*16 + lr][kk + lh]));
                    bl[2*p+0][0]=f[0]; bl[2*p+0][1]=f[2];
                    bl[2*p+1][0]=f[1]; bl[2*p+1][1]=f[3];
                }
#pragma unroll
                for (int mi = 0; mi < 2; mi++)
#pragma unroll
                    for (int nj = 0; nj < 4; nj++) {
                        float* a = acc[mi][half*4 + nj];
                        mma16816(a, ahf[mi], bh[nj][0], bh[nj][1]);
                        mma16816(a, ahf[mi], bl[nj][0], bl[nj][1]);
                        mma16816(a, alf[mi], bh[nj][0], bh[nj][1]);
                    }
            }
        }
        __syncthreads();
    }

#pragma unroll
    for (int mi = 0; mi < 2; mi++) {
        const int r = row0 + wm + mi*16 + (lane >> 2);
#pragma unroll
        for (int ni = 0; ni < 8; ni++) {
            const int c = col0 + wn + (ni>>2)*32 + (ni&3)*8 + (lane & 3)*2;
            float b0 = 0.f, b1 = 0.f;
            if (bias) { b0 = bias[c]; b1 = bias[c+1]; }
            const float v0 = acc[mi][ni][0]+b0, v1 = acc[mi][ni][1]+b1;
            const float v2 = acc[mi][ni][2]+b0, v3 = acc[mi][ni][3]+b1;
            if (Ch) {
                __nv_bfloat162 h2, l2;
                split2(v0, h2.x, l2.x); split2(v1, h2.y, l2.y);
                *(__nv_bfloat162*)(Ch + (long)r*ldc + c) = h2;
                *(__nv_bfloat162*)(Cl + (long)r*ldc + c) = l2;
                split2(v2, h2.x, l2.x); split2(v3, h2.y, l2.y);
                *(__nv_bfloat162*)(Ch + (long)(r+8)*ldc + c) = h2;
                *(__nv_bfloat162*)(Cl + (long)(r+8)*ldc + c) = l2;
            } else {
                *(float2*)(Cf + (long)r*ldc + c)     = make_float2(v0, v1);
                *(float2*)(Cf + (long)(r+8)*ldc + c) = make_float2(v2, v3);
            }
        }
    }
}

// ================= scores via mma: S = q @ k^T * 0.125 =====================
// per (b,h): A = q pair rows stride Dd, B = k pair rows stride Dd, K=64.
__global__ __launch_bounds__(256) void scores_mma(
    const __nv_bfloat16* __restrict__ qh, const __nv_bfloat16* __restrict__ ql,
    const __nv_bfloat16* __restrict__ kh, const __nv_bfloat16* __restrict__ kl,
    float* __restrict__ attn)
{
    __shared__ __nv_bfloat16 sAh[128][40], sAl[128][40];
    __shared__ __nv_bfloat16 sBh[128][40], sBl[128][40];
    const int tid = threadIdx.x;
    const int wid = tid >> 5, lane = tid & 31;
    const int bz = blockIdx.z;
    const long abase = (long)(bz>>3)*Ll*Dd + (bz&7)*Ee;
    const __nv_bfloat16* Ah = qh + abase;
    const __nv_bfloat16* Al = ql + abase;
    const __nv_bfloat16* Bh = kh + abase;
    const __nv_bfloat16* Bl = kl + abase;
    float* C = attn + (long)bz*Ll*Ll;
    const int row0 = blockIdx.y * 128, col0 = blockIdx.x * 128;
    const int wm = (wid & 3) * 32;
    const int wn = (wid >> 2) * 64;

    float acc[2][8][4];
#pragma unroll
    for (int i=0;i<2;i++)
#pragma unroll
        for (int j=0;j<8;j++)
#pragma unroll
            for (int t=0;t<4;t++) acc[i][j][t]=0.f;

    const int lr = lane & 15, lh = (lane >> 4) * 8;

    for (int k0 = 0; k0 < Ee; k0 += 32) {
#pragma unroll
        for (int s = 0; s < 2; s++) {
            const int idx = s * 256 + tid;
            const int r = idx >> 2, c = (idx & 3) * 8;
            *(uint4*)&sAh[r][c] = *(const uint4*)(Ah + (long)(row0+r)*Dd + k0 + c);
            *(uint4*)&sAl[r][c] = *(const uint4*)(Al + (long)(row0+r)*Dd + k0 + c);
            *(uint4*)&sBh[r][c] = *(const uint4*)(Bh + (long)(col0+r)*Dd + k0 + c);
            *(uint4*)&sBl[r][c] = *(const uint4*)(Bl + (long)(col0+r)*Dd + k0 + c);
        }
        __syncthreads();

#pragma unroll
        for (int kk = 0; kk < 32; kk += 16) {
            unsigned ahf[2][4], alf[2][4];
#pragma unroll
            for (int mi = 0; mi < 2; mi++) {
                ldm_x4(ahf[mi], sptr(&sAh[wm + mi*16 + lr][kk + lh]));
                ldm_x4(alf[mi], sptr(&sAl[wm + mi*16 + lr][kk + lh]));
            }
#pragma unroll
            for (int half = 0; half < 2; half++) {
                unsigned bh[4][2], bl[4][2];
#pragma unroll
                for (int p = 0; p < 2; p++) {
                    unsigned f[4];
                    ldm_x4(f, sptr(&sBh[wn + half*32 + p*16 + lr][kk + lh]));
                    bh[2*p+0][0]=f[0]; bh[2*p+0][1]=f[2];
                    bh[2*p+1][0]=f[1]; bh[2*p+1][1]=f[3];
                    ldm_x4(f, sptr(&sBl[wn + half*32 + p*16 + lr][kk + lh]));
                    bl[2*p+0][0]=f[0]; bl[2*p+0][1]=f[2];
                    bl[2*p+1][0]=f[1]; bl[2*p+1][1]=f[3];
                }
#pragma unroll
                for (int mi = 0; mi < 2; mi++)
#pragma unroll
                    for (int nj = 0; nj < 4; nj++) {
                        float* a = acc[mi][half*4 + nj];
                        mma16816(a, ahf[mi], bh[nj][0], bh[nj][1]);
                        mma16816(a, ahf[mi], bl[nj][0], bl[nj][1]);
                        mma16816(a, alf[mi], bh[nj][0], bh[nj][1]);
                    }
            }
        }
        __syncthreads();
    }

#pragma unroll
    for (int mi = 0; mi < 2; mi++) {
        const int r = row0 + wm + mi*16 + (lane >> 2);
#pragma unroll
        for (int ni = 0; ni < 8; ni++) {
            const int c = col0 + wn + (ni>>2)*32 + (ni&3)*8 + (lane & 3)*2;
            *(float2*)(C + (long)r*Ll + c) =
                make_float2(acc[mi][ni][0]*0.125f, acc[mi][ni][1]*0.125f);
            *(float2*)(C + (long)(r+8)*Ll + c) =
                make_float2(acc[mi][ni][2]*0.125f, acc[mi][ni][3]*0.125f);
        }
    }
}

// ================= attn @ v via mma: per (b,h), BM=128, BN=64 ==============
// A = attn pair [1024][1024]; B = vT pair [64][1024]; out o pair [l][h*64+e].
__global__ __launch_bounds__(256) void attnv_mma(
    const __nv_bfloat16* __restrict__ ah, const __nv_bfloat16* __restrict__ al,
    const __nv_bfloat16* __restrict__ vth, const __nv_bfloat16* __restrict__ vtl,
    __nv_bfloat16* __restrict__ oh, __nv_bfloat16* __restrict__ ol)
{
    __shared__ __nv_bfloat16 sAh[128][40], sAl[128][40];
    __shared__ __nv_bfloat16 sBh[64][40],  sBl[64][40];
    const int tid = threadIdx.x;
    const int wid = tid >> 5, lane = tid & 31;
    const int bz = blockIdx.z;
    const __nv_bfloat16* Abh = ah + (long)bz*Ll*Ll;
    const __nv_bfloat16* Abl = al + (long)bz*Ll*Ll;
    const __nv_bfloat16* Bbh = vth + (long)bz*Ee*Ll;
    const __nv_bfloat16* Bbl = vtl + (long)bz*Ee*Ll;
    const long obase = (long)(bz>>3)*Ll*Dd + (bz&7)*Ee;
    const int row0 = blockIdx.y * 128;
    const int wm = (wid & 3) * 32;      // warp m
    const int wn = (wid >> 2) * 32;     // warp n (2 warps cover 64)

    float acc[2][4][4];
#pragma unroll
    for (int i=0;i<2;i++)
#pragma unroll
        for (int j=0;j<4;j++)
#pragma unroll
            for (int t=0;t<4;t++) acc[i][j][t]=0.f;

    const int lr = lane & 15, lh = (lane >> 4) * 8;

    for (int k0 = 0; k0 < Ll; k0 += 32) {
#pragma unroll
        for (int s = 0; s < 2; s++) {
            const int idx = s * 256 + tid;
            const int r = idx >> 2, c = (idx & 3) * 8;
            *(uint4*)&sAh[r][c] = *(const uint4*)(Abh + (long)(row0+r)*Ll + k0 + c);
            *(uint4*)&sAl[r][c] = *(const uint4*)(Abl + (long)(row0+r)*Ll + k0 + c);
        }
        {
            const int r = tid >> 2, c = (tid & 3) * 8;
            *(uint4*)&sBh[r][c] = *(const uint4*)(Bbh + (long)r*Ll + k0 + c);
            *(uint4*)&sBl[r][c] = *(const uint4*)(Bbl + (long)r*Ll + k0 + c);
        }
        __syncthreads();

#pragma unroll
        for (int kk = 0; kk < 32; kk += 16) {
            unsigned ahf[2][4], alf[2][4];
#pragma unroll
            for (int mi = 0; mi < 2; mi++) {
                ldm_x4(ahf[mi], sptr(&sAh[wm + mi*16 + lr][kk + lh]));
                ldm_x4(alf[mi], sptr(&sAl[wm + mi*16 + lr][kk + lh]));
            }
            unsigned bh[4][2], bl[4][2];
#pragma unroll
            for (int p = 0; p < 2; p++) {
                unsigned f[4];
                ldm_x4(f, sptr(&sBh[wn + p*16 + lr][kk + lh]));
                bh[2*p+0][0]=f[0]; bh[2*p+0][1]=f[2];
                bh[2*p+1][0]=f[1]; bh[2*p+1][1]=f[3];
                ldm_x4(f, sptr(&sBl[wn + p*16 + lr][kk + lh]));
                bl[2*p+0][0]=f[0]; bl[2*p+0][1]=f[2];
                bl[2*p+1][0]=f[1]; bl[2*p+1][1]=f[3];
            }
#pragma unroll
            for (int mi = 0; mi < 2; mi++)
#pragma unroll
                for (int nj = 0; nj < 4; nj++) {
                    float* a = acc[mi][nj];
                    mma16816(a, ahf[mi], bh[nj][0], bh[nj][1]);
                    mma16816(a, ahf[mi], bl[nj][0], bl[nj][1]);
                    mma16816(a, alf[mi], bh[nj][0], bh[nj][1]);
                }
        }
        __syncthreads();
    }

#pragma unroll
    for (int mi = 0; mi < 2; mi++) {
        const int r = row0 + wm + mi*16 + (lane >> 2);
#pragma unroll
        for (int nj = 0; nj < 4; nj++) {
            const int c = wn + nj*8 + (lane & 3)*2;
            __nv_bfloat162 h2, l2;
            split2(acc[mi][nj][0], h2.x, l2.x);
            split2(acc[mi][nj][1], h2.y, l2.y);
            *(__nv_bfloat162*)(oh + obase + (long)r*Dd + c) = h2;
            *(__nv_bfloat162*)(ol + obase + (long)r*Dd + c) = l2;
            split2(acc[mi][nj][2], h2.x, l2.x);
            split2(acc[mi][nj][3], h2.y, l2.y);
            *(__nv_bfloat162*)(oh + obase + (long)(r+8)*Dd + c) = h2;
            *(__nv_bfloat162*)(ol + obase + (long)(r+8)*Dd + c) = l2;
        }
    }
}

// ================= split conversions =======================================
__global__ __launch_bounds__(256) void split_act(
    const float* __restrict__ x, __nv_bfloat16* __restrict__ h,
    __nv_bfloat16* __restrict__ l)
{
    const int i = blockIdx.x * 256 + threadIdx.x;
    const float v = x[i];
    __nv_bfloat16 hi, lo; split2(v, hi, lo);
    h[i] = hi; l[i] = lo;
}

// W [K][N] fp32 -> Wt hi/lo bf16 [N][K]
__global__ __launch_bounds__(256) void split_wt(
    const float* __restrict__ W, int Kdim, int Ndim,
    __nv_bfloat16* __restrict__ h, __nv_bfloat16* __restrict__ l)
{
    __shared__ float t[32][33];
    const int tx = threadIdx.x, ty = threadIdx.y;
    const int n0 = blockIdx.x * 32, k0 = blockIdx.y * 32;
#pragma unroll
    for (int j = 0; j < 4; j++)
        t[ty + 8 * j][tx] = W[(long)(k0 + ty + 8 * j) * Ndim + n0 + tx];
    __syncthreads();
#pragma unroll
    for (int j = 0; j < 4; j++) {
        const float v = t[tx][ty + 8 * j];
        __nv_bfloat16 hi, lo; split2(v, hi, lo);
        const long oidx = (long)(n0 + ty + 8 * j) * Kdim + k0 + tx;
        h[oidx] = hi; l[oidx] = lo;
    }
}

// v pair [b*1024+s][h*64+e] -> vT pair [(b*8+h)*64+e][s]
__global__ void vtrans(
    const __nv_bfloat16* __restrict__ vh, const __nv_bfloat16* __restrict__ vl,
    __nv_bfloat16* __restrict__ vth, __nv_bfloat16* __restrict__ vtl)
{
    __shared__ __nv_bfloat16 th[32][33], tl[32][33];
    const int tx = threadIdx.x, ty = threadIdx.y;   // (32, 8)
    const int bh = blockIdx.z;
    const int b = bh >> 3, h = bh & 7;
    const int s0 = blockIdx.x * 32, e0 = blockIdx.y * 32;
    const long ibase = (long)b*Ll*Dd + h*Ee;
#pragma unroll
    for (int j = 0; j < 4; j++) {
        const long off = ibase + (long)(s0 + ty + 8*j)*Dd + e0 + tx;
        th[ty+8*j][tx] = vh[off];
        tl[ty+8*j][tx] = vl[off];
    }
    __syncthreads();
    const long obase = (long)bh*Ee*Ll;
#pragma unroll
    for (int j = 0; j < 4; j++) {
        const long off = obase + (long)(e0 + ty + 8*j)*Ll + s0 + tx;
        vth[off] = th[tx][ty+8*j];
        vtl[off] = tl[tx][ty+8*j];
    }
}

// ---------------- softmax rows of 1024, in place + bf16 pair output --------
__global__ __launch_bounds__(256) void softmax_split(
    float* __restrict__ a, __nv_bfloat16* __restrict__ ah,
    __nv_bfloat16* __restrict__ al)
{
    const long row = blockIdx.x;
    float* p = a + row * (long)Ll;
    __nv_bfloat16* ph = ah + row * (long)Ll;
    __nv_bfloat16* pl = al + row * (long)Ll;
    const int tid = threadIdx.x;
    float v[4];
    float m = -1e30f;
#pragma unroll
    for (int i=0;i<4;i++){ v[i] = p[tid + 256*i]; m = fmaxf(m, v[i]); }
#pragma unroll
    for (int off=16; off; off>>=1) m = fmaxf(m, __shfl_xor_sync(0xffffffffu, m, off));
    __shared__ float sm[8], ss[8];
    const int w = tid >> 5, lane = tid & 31;
    if (lane==0) sm[w] = m;
    __syncthreads();
    m = sm[0];
#pragma unroll
    for (int i=1;i<8;i++) m = fmaxf(m, sm[i]);
    float s = 0.f;
#pragma unroll
    for (int i=0;i<4;i++){ v[i] = __expf(v[i]-m); s += v[i]; }
#pragma unroll
    for (int off=16; off; off>>=1) s += __shfl_xor_sync(0xffffffffu, s, off);
    if (lane==0) ss[w] = s;
    __syncthreads();
    s = 0.f;
#pragma unroll
    for (int i=0;i<8;i++) s += ss[i];
    const float inv = 1.f / s;
#pragma unroll
    for (int i=0;i<4;i++){
        const int c = tid + 256*i;
        const float val = v[i] * inv;
        p[c] = val;
        __nv_bfloat16 hi, lo; split2(val, hi, lo);
        ph[c] = hi; pl[c] = lo;
    }
}

// ---------------- out = LayerNorm(xa + xb) (+ optional bf16 pair) ----------
__global__ __launch_bounds__(128) void add_ln(
    const float* __restrict__ xa, const float* __restrict__ xb,
    const float* __restrict__ g, const float* __restrict__ bt,
    float* __restrict__ out, __nv_bfloat16* __restrict__ oh,
    __nv_bfloat16* __restrict__ ol)
{
    const int row = blockIdx.x, tid = threadIdx.x;
    const float* pa = xa + (long)row*Dd;
    const float* pb = xb + (long)row*Dd;
    float v[4]; float s1=0.f, s2=0.f;
#pragma unroll
    for (int i=0;i<4;i++){ int c = tid + 128*i; v[i] = pa[c] + pb[c]; s1 += v[i]; s2 += v[i]*v[i]; }
#pragma unroll
    for (int off=16; off; off>>=1){
        s1 += __shfl_xor_sync(0xffffffffu, s1, off);
        s2 += __shfl_xor_sync(0xffffffffu, s2, off);
    }
    __shared__ float r1[4], r2[4];
    const int w = tid >> 5, lane = tid & 31;
    if (lane==0){ r1[w]=s1; r2[w]=s2; }
    __syncthreads();
    s1 = r1[0]+r1[1]+r1[2]+r1[3];
    s2 = r2[0]+r2[1]+r2[2]+r2[3];
    const float mean = s1 * (1.f/Dd);
    const float var  = s2 * (1.f/Dd) - mean*mean;
    const float rstd = rsqrtf(var + 1e-5f);
    float* po = out + (long)row*Dd;
#pragma unroll
    for (int i=0;i<4;i++){
        const int c = tid + 128*i;
        const float val = (v[i]-mean)*rstd*g[c] + bt[c];
        po[c] = val;
        if (oh) {
            __nv_bfloat16 hi, lo; split2(val, hi, lo);
            oh[(long)row*Dd + c] = hi;
            ol[(long)row*Dd + c] = lo;
        }
    }
}

// ============ 64x64 GEMM for small N problems (Wx, Wdt) ====================
__global__ __launch_bounds__(256) void gemm64(
    const float* __restrict__ A, int lda,
    const float* __restrict__ W, int ldw,
    const float* __restrict__ bias,
    float* __restrict__ C, int ldc, int K, int act)
{
    __shared__ float As[16][64];
    __shared__ float Ws[16][68];
    const int tid = threadIdx.x;
    const int row0 = blockIdx.y * 64;
    const int col0 = blockIdx.x * 64;
    const int ar = tid >> 2, ac = (tid & 3) * 4;
    const int br = tid >> 4, bc = (tid & 15) * 4;
    const int tm = (tid & 15) * 4, tn = (tid >> 4) * 4;
    float acc[4][4];
#pragma unroll
    for (int i=0;i<4;i++)
#pragma unroll
        for (int j=0;j<4;j++) acc[i][j]=0.f;

    for (int k0 = 0; k0 < K; k0 += 16) {
        float4 a4 = *(const float4*)(A + (long)(row0+ar)*lda + k0 + ac);
        As[ac+0][ar]=a4.x; As[ac+1][ar]=a4.y; As[ac+2][ar]=a4.z; As[ac+3][ar]=a4.w;
        float4 b4 = *(const float4*)(W + (long)(k0+br)*ldw + col0 + bc);
        *(float4*)&Ws[br][bc] = b4;
        __syncthreads();
#pragma unroll
        for (int k=0;k<16;k++){
            float a[4], b[4];
#pragma unroll
            for (int i=0;i<4;i++) a[i]=As[k][tm+i];
#pragma unroll
            for (int j=0;j<4;j++) b[j]=Ws[k][tn+j];
#pragma unroll
            for (int i=0;i<4;i++)
#pragma unroll
                for (int j=0;j<4;j++) acc[i][j]=fmaf(a[i],b[j],acc[i][j]);
        }
        __syncthreads();
    }
#pragma unroll
    for (int j=0;j<4;j++){
        int c = col0 + tn + j;
        float bvv = bias ? bias[c] : 0.f;
#pragma unroll
        for (int i=0;i<4;i++){
            float vv = acc[i][j] + bvv;
            if (act == 1) vv = (vv > 20.f) ? vv : log1pf(__expf(vv));
            C[(long)(row0+tm+i)*ldc + c] = vv;
        }
    }
}

// ---------------- depthwise causal conv (K=4) + bias + silu ----------------
__global__ __launch_bounds__(256) void conv_silu_k(
    const float* __restrict__ xz, const float* __restrict__ w,
    const float* __restrict__ cb, float* __restrict__ xc)
{
    const long idx = (long)blockIdx.x*256 + threadIdx.x;
    const int d = (int)(idx & (DINc-1));
    const long row = idx >> 10;
    const int l = (int)(row & (Ll-1));
    float acc = cb[d];
#pragma unroll
    for (int j=0;j<4;j++) {
        int ll = l - 3 + j;
        if (ll >= 0)
            acc = fmaf(xz[(row-3+j)*(2*DINc) + d], w[d*4+j], acc);
    }
    xc[idx] = acc / (1.f + __expf(-acc));
}

// ---------------- selective scan, outputs bf16 pair ------------------------
__global__ __launch_bounds__(128) void scan_k(
    const float* __restrict__ dt, const float* __restrict__ xc,
    const float* __restrict__ dbl, const float* __restrict__ xz,
    const float* __restrict__ Alog, const float* __restrict__ Dp,
    __nv_bfloat16* __restrict__ yh, __nv_bfloat16* __restrict__ yl)
{
    const int tid = threadIdx.x;
    const int n  = tid & 15;
    const int dl = tid >> 4;
    const int b  = blockIdx.x >> 7;
    const int d  = (blockIdx.x & 127)*8 + dl;
    const float Aa = -__expf(Alog[d*Nn + n]);
    const float Dv = Dp[d];
    float h = 0.f;
    const long base = (long)b * Ll;

    float dtv = dt[base*DINc + d];
    float xcv = xc[base*DINc + d];
    float Bv  = dbl[base*64 + 32 + n];
    float Cv  = dbl[base*64 + 48 + n];
    float zv  = xz[base*(2*DINc) + DINc + d];

    for (int t = 0; t < Ll; t++) {
        const float dtc = dtv, xcc = xcv, Bc = Bv, Cc = Cv, zc = zv;
        if (t + 1 < Ll) {
            const long r2 = base + t + 1;
            dtv = dt[r2*DINc + d];
            xcv = xc[r2*DINc + d];
            Bv  = dbl[r2*64 + 32 + n];
            Cv  = dbl[r2*64 + 48 + n];
            zv  = xz[r2*(2*DINc) + DINc + d];
        }
        const float dA = __expf(dtc * Aa);
        h = fmaf(h, dA, dtc * xcc * Bc);
        float p = h * Cc;
        p += __shfl_xor_sync(0xffffffffu, p, 8);
        p += __shfl_xor_sync(0xffffffffu, p, 4);
        p += __shfl_xor_sync(0xffffffffu, p, 2);
        p += __shfl_xor_sync(0xffffffffu, p, 1);
        if (n == 0) {
            const float sz = zc / (1.f + __expf(-zc));
            const float val = (p + xcc * Dv) * sz;
            __nv_bfloat16 hi, lo; split2(val, hi, lo);
            yh[(base+t)*DINc + d] = hi;
            yl[(base+t)*DINc + d] = lo;
        }
    }
}

// ---------------- launch ----------------------------------------------------
extern "C" void kernel_launch(void* const* d_in, const int* in_sizes, int n_in,
                              void* d_out, int out_size)
{
    const float* x    = (const float*)d_in[0];
    const float* Wq   = (const float*)d_in[1];
    const float* bq   = (const float*)d_in[2];
    const float* Wk   = (const float*)d_in[3];
    const float* bk   = (const float*)d_in[4];
    const float* Wv   = (const float*)d_in[5];
    const float* bv   = (const float*)d_in[6];
    const float* Wo   = (const float*)d_in[7];
    const float* bo   = (const float*)d_in[8];
    const float* ln1g = (const float*)d_in[9];
    const float* ln1b = (const float*)d_in[10];
    const float* ln2g = (const float*)d_in[11];
    const float* ln2b = (const float*)d_in[12];
    const float* Win  = (const float*)d_in[13];
    const float* cw   = (const float*)d_in[14];
    const float* cb   = (const float*)d_in[15];
    const float* Wx   = (const float*)d_in[16];
    const float* Wdt  = (const float*)d_in[17];
    const float* bdt  = (const float*)d_in[18];
    const float* Alog = (const float*)d_in[19];
    const float* Dp   = (const float*)d_in[20];
    const float* Wout = (const float*)d_in[21];

    float* out  = (float*)d_out;
    float* attn = out + (size_t)Bb*Ll*Dd;

    float *t1,*x1,*xz,*xc,*db,*dtb,*y;
    cudaGetSymbolAddress((void**)&t1, g_t1);
    cudaGetSymbolAddress((void**)&x1, g_x1);
    cudaGetSymbolAddress((void**)&xz, g_xz);
    cudaGetSymbolAddress((void**)&xc, g_xc);
    cudaGetSymbolAddress((void**)&db, g_db);
    cudaGetSymbolAddress((void**)&dtb,g_dt);
    cudaGetSymbolAddress((void**)&y,  g_y);

    __nv_bfloat16 *xh,*xl,*qh,*ql,*kh,*kl,*vh,*vl,*vth,*vtl,*ah,*al,*oh,*ol,*x1h,*x1l,*yah,*yal;
    __nv_bfloat16 *Wqh,*Wql,*Wkh,*Wkl,*Wvh,*Wvl,*Woh,*Wol,*Wih,*Wil,*Wuh,*Wul;
    cudaGetSymbolAddress((void**)&xh,  g_xh);  cudaGetSymbolAddress((void**)&xl,  g_xl);
    cudaGetSymbolAddress((void**)&qh,  g_qh);  cudaGetSymbolAddress((void**)&ql,  g_ql);
    cudaGetSymbolAddress((void**)&kh,  g_kh);  cudaGetSymbolAddress((void**)&kl,  g_kl);
    cudaGetSymbolAddress((void**)&vh,  g_vh);  cudaGetSymbolAddress((void**)&vl,  g_vl);
    cudaGetSymbolAddress((void**)&vth, g_vth); cudaGetSymbolAddress((void**)&vtl, g_vtl);
    cudaGetSymbolAddress((void**)&ah,  g_ah);  cudaGetSymbolAddress((void**)&al,  g_al);
    cudaGetSymbolAddress((void**)&oh,  g_oh);  cudaGetSymbolAddress((void**)&ol,  g_ol);
    cudaGetSymbolAddress((void**)&x1h, g_x1h); cudaGetSymbolAddress((void**)&x1l, g_x1l);
    cudaGetSymbolAddress((void**)&yah, g_yah); cudaGetSymbolAddress((void**)&yal, g_yal);
    cudaGetSymbolAddress((void**)&Wqh, g_Wqh); cudaGetSymbolAddress((void**)&Wql, g_Wql);
    cudaGetSymbolAddress((void**)&Wkh, g_Wkh); cudaGetSymbolAddress((void**)&Wkl, g_Wkl);
    cudaGetSymbolAddress((void**)&Wvh, g_Wvh); cudaGetSymbolAddress((void**)&Wvl, g_Wvl);
    cudaGetSymbolAddress((void**)&Woh, g_Woh); cudaGetSymbolAddress((void**)&Wol, g_Wol);
    cudaGetSymbolAddress((void**)&Wih, g_Wih); cudaGetSymbolAddress((void**)&Wil, g_Wil);
    cudaGetSymbolAddress((void**)&Wuh, g_Wuh); cudaGetSymbolAddress((void**)&Wul, g_Wul);

    // weight conversions (transpose + hi/lo split)
    split_wt<<<dim3(Dd/32, Dd/32), dim3(32,8)>>>(Wq, Dd, Dd, Wqh, Wql);
    split_wt<<<dim3(Dd/32, Dd/32), dim3(32,8)>>>(Wk, Dd, Dd, Wkh, Wkl);
    split_wt<<<dim3(Dd/32, Dd/32), dim3(32,8)>>>(Wv, Dd, Dd, Wvh, Wvl);
    split_wt<<<dim3(Dd/32, Dd/32), dim3(32,8)>>>(Wo, Dd, Dd, Woh, Wol);
    split_wt<<<dim3(2*DINc/32, Dd/32), dim3(32,8)>>>(Win, Dd, 2*DINc, Wih, Wil);
    split_wt<<<dim3(Dd/32, DINc/32), dim3(32,8)>>>(Wout, DINc, Dd, Wuh, Wul);

    // x split + QKV (mma, bf16-pair outputs)
    split_act<<<(Mrows*Dd)/256, 256>>>(x, xh, xl);
    gemm_mma<<<dim3(Dd/128, Mrows/128), 256>>>(xh, xl, Wqh, Wql, bq, nullptr, qh, ql, Dd, Dd);
    gemm_mma<<<dim3(Dd/128, Mrows/128), 256>>>(xh, xl, Wkh, Wkl, bk, nullptr, kh, kl, Dd, Dd);
    gemm_mma<<<dim3(Dd/128, Mrows/128), 256>>>(xh, xl, Wvh, Wvl, bv, nullptr, vh, vl, Dd, Dd);
    vtrans<<<dim3(Ll/32, Ee/32, Bb*Hh), dim3(32,8)>>>(vh, vl, vth, vtl);

    // attention
    scores_mma<<<dim3(Ll/128, Ll/128, Bb*Hh), 256>>>(qh, ql, kh, kl, attn);
    softmax_split<<<Bb*Hh*Ll, 256>>>(attn, ah, al);
    attnv_mma<<<dim3(1, Ll/128, Bb*Hh), 256>>>(ah, al, vth, vtl, oh, ol);

    // o @ Wo + bo (mma) ; x1 = LN(x + .) with pair output
    gemm_mma<<<dim3(Dd/128, Mrows/128), 256>>>(oh, ol, Woh, Wol, bo, t1, nullptr, nullptr, Dd, Dd);
    add_ln<<<Mrows, 128>>>(x, t1, ln1g, ln1b, x1, x1h, x1l);

    // mamba in-proj (mma, N=2048)
    gemm_mma<<<dim3(2*DINc/128, Mrows/128), 256>>>(x1h, x1l, Wih, Wil, nullptr, xz, nullptr, nullptr, 2*DINc, Dd);

    // conv + silu
    conv_silu_k<<<(Mrows*DINc)/256, 256>>>(xz, cw, cb, xc);
    // dbl = xc @ Wx   (N=64, K=1024)
    gemm64<<<dim3(1, Mrows/64), 256>>>(xc, DINc, Wx, 64, nullptr, db, 64, DINc, 0);
    // dt = softplus(dbl[:, :32] @ Wdt + bdt)
    gemm64<<<dim3(DINc/64, Mrows/64), 256>>>(db, 64, Wdt, DINc, bdt, dtb, DINc, Rr, 1);
    // selective scan -> ya bf16 pair
    scan_k<<<Bb*(DINc/8), 128>>>(dtb, xc, db, xz, Alog, Dp, yah, yal);

    // out-proj (mma, K=1024) + final LN
    gemm_mma<<<dim3(Dd/128, Mrows/128), 256>>>(yah, yal, Wuh, Wul, nullptr, y, nullptr, nullptr, Dd, DINc);
    add_ln<<<Mrows, 128>>>(x1, y, ln2g, ln2b, out, nullptr, nullptr);

    (void)in_sizes; (void)n_in; (void)out_size;
}

// round 12
// speedup vs baseline: 2.1740x; 1.1620x over previous
#include <cuda_runtime.h>
#include <cuda_bf16.h>
#include <math.h>

// ---------------- problem constants ----------------
#define Bb   4
#define Ll   1024
#define Dd   512
#define Hh   8
#define Ee   64
#define DINc 1024
#define Nn   16
#define Rr   32
#define Mrows (Bb*Ll)          // 4096

// ---------------- fp32 scratch ----------------
__device__ float g_t1[Mrows*Dd];
__device__ float g_x1[Mrows*Dd];
__device__ float g_xz[(size_t)Mrows*2*DINc];
__device__ float g_xc[(size_t)Mrows*DINc];
__device__ float g_db[Mrows*64];
__device__ float g_dt[(size_t)Mrows*DINc];
__device__ float g_y [Mrows*Dd];

// ---------------- bf16 pair scratch (hi/lo) ----------------
__device__ __nv_bfloat16 g_xh [Mrows*Dd],   g_xl [Mrows*Dd];
__device__ __nv_bfloat16 g_qh [Mrows*Dd],   g_ql [Mrows*Dd];
__device__ __nv_bfloat16 g_kh [Mrows*Dd],   g_kl [Mrows*Dd];
__device__ __nv_bfloat16 g_vh [Mrows*Dd],   g_vl [Mrows*Dd];
__device__ __nv_bfloat16 g_vth[(size_t)Bb*Hh*Ee*Ll], g_vtl[(size_t)Bb*Hh*Ee*Ll];
__device__ __nv_bfloat16 g_ah [(size_t)Bb*Hh*Ll*Ll], g_al [(size_t)Bb*Hh*Ll*Ll];
__device__ __nv_bfloat16 g_oh [Mrows*Dd],   g_ol [Mrows*Dd];
__device__ __nv_bfloat16 g_x1h[Mrows*Dd],   g_x1l[Mrows*Dd];
__device__ __nv_bfloat16 g_yah[(size_t)Mrows*DINc], g_yal[(size_t)Mrows*DINc];
// transposed weights [N][K]
__device__ __nv_bfloat16 g_Wqh[Dd*Dd],  g_Wql[Dd*Dd];
__device__ __nv_bfloat16 g_Wkh[Dd*Dd],  g_Wkl[Dd*Dd];
__device__ __nv_bfloat16 g_Wvh[Dd*Dd],  g_Wvl[Dd*Dd];
__device__ __nv_bfloat16 g_Woh[Dd*Dd],  g_Wol[Dd*Dd];
__device__ __nv_bfloat16 g_Wih[(size_t)Dd*2*DINc], g_Wil[(size_t)Dd*2*DINc];
__device__ __nv_bfloat16 g_Wuh[(size_t)DINc*Dd],   g_Wul[(size_t)DINc*Dd];

// ---------------- helpers ----------------
__device__ __forceinline__ unsigned sptr(const void* p){
    unsigned a;
    asm("{ .reg .u64 t; cvta.to.shared.u64 t, %1; cvt.u32.u64 %0, t; }" : "=r"(a) : "l"(p));
    return a;
}
__device__ __forceinline__ void ldm_x4(unsigned* f, unsigned addr){
    asm volatile("ldmatrix.sync.aligned.m8n8.x4.shared.b16 {%0,%1,%2,%3}, [%4];"
        : "=r"(f[0]), "=r"(f[1]), "=r"(f[2]), "=r"(f[3]) : "r"(addr));
}
__device__ __forceinline__ void mma16816(float* d, const unsigned* a,
                                         unsigned b0, unsigned b1){
    asm volatile(
        "mma.sync.aligned.m16n8k16.row.col.f32.bf16.bf16.f32 "
        "{%0,%1,%2,%3}, {%4,%5,%6,%7}, {%8,%9}, {%0,%1,%2,%3};"
        : "+f"(d[0]), "+f"(d[1]), "+f"(d[2]), "+f"(d[3])
        : "r"(a[0]), "r"(a[1]), "r"(a[2]), "r"(a[3]), "r"(b0), "r"(b1));
}
__device__ __forceinline__ void split2(float v, __nv_bfloat16& h, __nv_bfloat16& l){
    h = __float2bfloat16(v);
    l = __float2bfloat16(v - __bfloat162float(h));
}

// ================= unified 3x-split tensor-core GEMM =======================
// C[M,N] = (Ah+Al)[M,K] @ (Bh+Bl)^T, B stored [N][K]. BM=BN=128, BK=32.
// Output: if Ch != nullptr, write bf16 hi/lo pair; else fp32 to Cf.
__global__ __launch_bounds__(256) void gemm_mma(
    const __nv_bfloat16* __restrict__ Ah, const __nv_bfloat16* __restrict__ Al,
    const __nv_bfloat16* __restrict__ Bh, const __nv_bfloat16* __restrict__ Bl,
    const float* __restrict__ bias,
    float* __restrict__ Cf, __nv_bfloat16* __restrict__ Ch,
    __nv_bfloat16* __restrict__ Cl, int ldc, int K)
{
    __shared__ __nv_bfloat16 sAh[128][40], sAl[128][40];
    __shared__ __nv_bfloat16 sBh[128][40], sBl[128][40];
    const int tid = threadIdx.x;
    const int wid = tid >> 5, lane = tid & 31;
    const int row0 = blockIdx.y * 128, col0 = blockIdx.x * 128;
    const int wm = (wid & 3) * 32;
    const int wn = (wid >> 2) * 64;

    float acc[2][8][4];
#pragma unroll
    for (int i=0;i<2;i++)
#pragma unroll
        for (int j=0;j<8;j++)
#pragma unroll
            for (int t=0;t<4;t++) acc[i][j][t]=0.f;

    const int lr = lane & 15, lh = (lane >> 4) * 8;

    for (int k0 = 0; k0 < K; k0 += 32) {
#pragma unroll
        for (int s = 0; s < 2; s++) {
            const int idx = s * 256 + tid;
            const int r = idx >> 2, c = (idx & 3) * 8;
            const long goff = (long)(row0 + r) * K + k0 + c;
            const long hoff = (long)(col0 + r) * K + k0 + c;
            *(uint4*)&sAh[r][c] = *(const uint4*)(Ah + goff);
            *(uint4*)&sAl[r][c] = *(const uint4*)(Al + goff);
            *(uint4*)&sBh[r][c] = *(const uint4*)(Bh + hoff);
            *(uint4*)&sBl[r][c] = *(const uint4*)(Bl + hoff);
        }
        __syncthreads();

#pragma unroll
        for (int kk = 0; kk < 32; kk += 16) {
            unsigned ahf[2][4], alf[2][4];
#pragma unroll
            for (int mi = 0; mi < 2; mi++) {
                ldm_x4(ahf[mi], sptr(&sAh[wm + mi*16 + lr][kk + lh]));
                ldm_x4(alf[mi], sptr(&sAl[wm + mi*16 + lr][kk + lh]));
            }
#pragma unroll
            for (int half = 0; half < 2; half++) {
                unsigned bh[4][2], bl[4][2];
#pragma unroll
                for (int p = 0; p < 2; p++) {
                    unsigned f[4];
                    ldm_x4(f, sptr(&sBh[wn + half*32 + p*16 + lr][kk + lh]));
                    bh[2*p+0][0]=f[0]; bh[2*p+0][1]=f[2];
                    bh[2*p+1][0]=f[1]; bh[2*p+1][1]=f[3];
                    ldm_x4(f, sptr(&sBl[wn + half*32 + p*16 + lr][kk + lh]));
                    bl[2*p+0][0]=f[0]; bl[2*p+0][1]=f[2];
                    bl[2*p+1][0]=f[1]; bl[2*p+1][1]=f[3];
                }
#pragma unroll
                for (int mi = 0; mi < 2; mi++)
#pragma unroll
                    for (int nj = 0; nj < 4; nj++) {
                        float* a = acc[mi][half*4 + nj];
                        mma16816(a, ahf[mi], bh[nj][0], bh[nj][1]);
                        mma16816(a, ahf[mi], bl[nj][0], bl[nj][1]);
                        mma16816(a, alf[mi], bh[nj][0], bh[nj][1]);
                    }
            }
        }
        __syncthreads();
    }

#pragma unroll
    for (int mi = 0; mi < 2; mi++) {
        const int r = row0 + wm + mi*16 + (lane >> 2);
#pragma unroll
        for (int ni = 0; ni < 8; ni++) {
            const int c = col0 + wn + (ni>>2)*32 + (ni&3)*8 + (lane & 3)*2;
            float b0 = 0.f, b1 = 0.f;
            if (bias) { b0 = bias[c]; b1 = bias[c+1]; }
            const float v0 = acc[mi][ni][0]+b0, v1 = acc[mi][ni][1]+b1;
            const float v2 = acc[mi][ni][2]+b0, v3 = acc[mi][ni][3]+b1;
            if (Ch) {
                __nv_bfloat162 h2, l2;
                split2(v0, h2.x, l2.x); split2(v1, h2.y, l2.y);
                *(__nv_bfloat162*)(Ch + (long)r*ldc + c) = h2;
                *(__nv_bfloat162*)(Cl + (long)r*ldc + c) = l2;
                split2(v2, h2.x, l2.x); split2(v3, h2.y, l2.y);
                *(__nv_bfloat162*)(Ch + (long)(r+8)*ldc + c) = h2;
                *(__nv_bfloat162*)(Cl + (long)(r+8)*ldc + c) = l2;
            } else {
                *(float2*)(Cf + (long)r*ldc + c)     = make_float2(v0, v1);
                *(float2*)(Cf + (long)(r+8)*ldc + c) = make_float2(v2, v3);
            }
        }
    }
}

// ================= scores via mma: S = q @ k^T * 0.125 =====================
__global__ __launch_bounds__(256) void scores_mma(
    const __nv_bfloat16* __restrict__ qh, const __nv_bfloat16* __restrict__ ql,
    const __nv_bfloat16* __restrict__ kh, const __nv_bfloat16* __restrict__ kl,
    float* __restrict__ attn)
{
    __shared__ __nv_bfloat16 sAh[128][40], sAl[128][40];
    __shared__ __nv_bfloat16 sBh[128][40], sBl[128][40];
    const int tid = threadIdx.x;
    const int wid = tid >> 5, lane = tid & 31;
    const int bz = blockIdx.z;
    const long abase = (long)(bz>>3)*Ll*Dd + (bz&7)*Ee;
    const __nv_bfloat16* Ah = qh + abase;
    const __nv_bfloat16* Al = ql + abase;
    const __nv_bfloat16* Bh = kh + abase;
    const __nv_bfloat16* Bl = kl + abase;
    float* C = attn + (long)bz*Ll*Ll;
    const int row0 = blockIdx.y * 128, col0 = blockIdx.x * 128;
    const int wm = (wid & 3) * 32;
    const int wn = (wid >> 2) * 64;

    float acc[2][8][4];
#pragma unroll
    for (int i=0;i<2;i++)
#pragma unroll
        for (int j=0;j<8;j++)
#pragma unroll
            for (int t=0;t<4;t++) acc[i][j][t]=0.f;

    const int lr = lane & 15, lh = (lane >> 4) * 8;

    for (int k0 = 0; k0 < Ee; k0 += 32) {
#pragma unroll
        for (int s = 0; s < 2; s++) {
            const int idx = s * 256 + tid;
            const int r = idx >> 2, c = (idx & 3) * 8;
            *(uint4*)&sAh[r][c] = *(const uint4*)(Ah + (long)(row0+r)*Dd + k0 + c);
            *(uint4*)&sAl[r][c] = *(const uint4*)(Al + (long)(row0+r)*Dd + k0 + c);
            *(uint4*)&sBh[r][c] = *(const uint4*)(Bh + (long)(col0+r)*Dd + k0 + c);
            *(uint4*)&sBl[r][c] = *(const uint4*)(Bl + (long)(col0+r)*Dd + k0 + c);
        }
        __syncthreads();

#pragma unroll
        for (int kk = 0; kk < 32; kk += 16) {
            unsigned ahf[2][4], alf[2][4];
#pragma unroll
            for (int mi = 0; mi < 2; mi++) {
                ldm_x4(ahf[mi], sptr(&sAh[wm + mi*16 + lr][kk + lh]));
                ldm_x4(alf[mi], sptr(&sAl[wm + mi*16 + lr][kk + lh]));
            }
#pragma unroll
            for (int half = 0; half < 2; half++) {
                unsigned bh[4][2], bl[4][2];
#pragma unroll
                for (int p = 0; p < 2; p++) {
                    unsigned f[4];
                    ldm_x4(f, sptr(&sBh[wn + half*32 + p*16 + lr][kk + lh]));
                    bh[2*p+0][0]=f[0]; bh[2*p+0][1]=f[2];
                    bh[2*p+1][0]=f[1]; bh[2*p+1][1]=f[3];
                    ldm_x4(f, sptr(&sBl[wn + half*32 + p*16 + lr][kk + lh]));
                    bl[2*p+0][0]=f[0]; bl[2*p+0][1]=f[2];
                    bl[2*p+1][0]=f[1]; bl[2*p+1][1]=f[3];
                }
#pragma unroll
                for (int mi = 0; mi < 2; mi++)
#pragma unroll
                    for (int nj = 0; nj < 4; nj++) {
                        float* a = acc[mi][half*4 + nj];
                        mma16816(a, ahf[mi], bh[nj][0], bh[nj][1]);
                        mma16816(a, ahf[mi], bl[nj][0], bl[nj][1]);
                        mma16816(a, alf[mi], bh[nj][0], bh[nj][1]);
                    }
            }
        }
        __syncthreads();
    }

#pragma unroll
    for (int mi = 0; mi < 2; mi++) {
        const int r = row0 + wm + mi*16 + (lane >> 2);
#pragma unroll
        for (int ni = 0; ni < 8; ni++) {
            const int c = col0 + wn + (ni>>2)*32 + (ni&3)*8 + (lane & 3)*2;
            *(float2*)(C + (long)r*Ll + c) =
                make_float2(acc[mi][ni][0]*0.125f, acc[mi][ni][1]*0.125f);
            *(float2*)(C + (long)(r+8)*Ll + c) =
                make_float2(acc[mi][ni][2]*0.125f, acc[mi][ni][3]*0.125f);
        }
    }
}

// ================= attn @ v via mma: per (b,h), BM=128, BN=64 ==============
__global__ __launch_bounds__(256) void attnv_mma(
    const __nv_bfloat16* __restrict__ ah, const __nv_bfloat16* __restrict__ al,
    const __nv_bfloat16* __restrict__ vth, const __nv_bfloat16* __restrict__ vtl,
    __nv_bfloat16* __restrict__ oh, __nv_bfloat16* __restrict__ ol)
{
    __shared__ __nv_bfloat16 sAh[128][40], sAl[128][40];
    __shared__ __nv_bfloat16 sBh[64][40],  sBl[64][40];
    const int tid = threadIdx.x;
    const int wid = tid >> 5, lane = tid & 31;
    const int bz = blockIdx.z;
    const __nv_bfloat16* Abh = ah + (long)bz*Ll*Ll;
    const __nv_bfloat16* Abl = al + (long)bz*Ll*Ll;
    const __nv_bfloat16* Bbh = vth + (long)bz*Ee*Ll;
    const __nv_bfloat16* Bbl = vtl + (long)bz*Ee*Ll;
    const long obase = (long)(bz>>3)*Ll*Dd + (bz&7)*Ee;
    const int row0 = blockIdx.y * 128;
    const int wm = (wid & 3) * 32;
    const int wn = (wid >> 2) * 32;

    float acc[2][4][4];
#pragma unroll
    for (int i=0;i<2;i++)
#pragma unroll
        for (int j=0;j<4;j++)
#pragma unroll
            for (int t=0;t<4;t++) acc[i][j][t]=0.f;

    const int lr = lane & 15, lh = (lane >> 4) * 8;

    for (int k0 = 0; k0 < Ll; k0 += 32) {
#pragma unroll
        for (int s = 0; s < 2; s++) {
            const int idx = s * 256 + tid;
            const int r = idx >> 2, c = (idx & 3) * 8;
            *(uint4*)&sAh[r][c] = *(const uint4*)(Abh + (long)(row0+r)*Ll + k0 + c);
            *(uint4*)&sAl[r][c] = *(const uint4*)(Abl + (long)(row0+r)*Ll + k0 + c);
        }
        {
            const int r = tid >> 2, c = (tid & 3) * 8;
            *(uint4*)&sBh[r][c] = *(const uint4*)(Bbh + (long)r*Ll + k0 + c);
            *(uint4*)&sBl[r][c] = *(const uint4*)(Bbl + (long)r*Ll + k0 + c);
        }
        __syncthreads();

#pragma unroll
        for (int kk = 0; kk < 32; kk += 16) {
            unsigned ahf[2][4], alf[2][4];
#pragma unroll
            for (int mi = 0; mi < 2; mi++) {
                ldm_x4(ahf[mi], sptr(&sAh[wm + mi*16 + lr][kk + lh]));
                ldm_x4(alf[mi], sptr(&sAl[wm + mi*16 + lr][kk + lh]));
            }
            unsigned bh[4][2], bl[4][2];
#pragma unroll
            for (int p = 0; p < 2; p++) {
                unsigned f[4];
                ldm_x4(f, sptr(&sBh[wn + p*16 + lr][kk + lh]));
                bh[2*p+0][0]=f[0]; bh[2*p+0][1]=f[2];
                bh[2*p+1][0]=f[1]; bh[2*p+1][1]=f[3];
                ldm_x4(f, sptr(&sBl[wn + p*16 + lr][kk + lh]));
                bl[2*p+0][0]=f[0]; bl[2*p+0][1]=f[2];
                bl[2*p+1][0]=f[1]; bl[2*p+1][1]=f[3];
            }
#pragma unroll
            for (int mi = 0; mi < 2; mi++)
#pragma unroll
                for (int nj = 0; nj < 4; nj++) {
                    float* a = acc[mi][nj];
                    mma16816(a, ahf[mi], bh[nj][0], bh[nj][1]);
                    mma16816(a, ahf[mi], bl[nj][0], bl[nj][1]);
                    mma16816(a, alf[mi], bh[nj][0], bh[nj][1]);
                }
        }
        __syncthreads();
    }

#pragma unroll
    for (int mi = 0; mi < 2; mi++) {
        const int r = row0 + wm + mi*16 + (lane >> 2);
#pragma unroll
        for (int nj = 0; nj < 4; nj++) {
            const int c = wn + nj*8 + (lane & 3)*2;
            __nv_bfloat162 h2, l2;
            split2(acc[mi][nj][0], h2.x, l2.x);
            split2(acc[mi][nj][1], h2.y, l2.y);
            *(__nv_bfloat162*)(oh + obase + (long)r*Dd + c) = h2;
            *(__nv_bfloat162*)(ol + obase + (long)r*Dd + c) = l2;
            split2(acc[mi][nj][2], h2.x, l2.x);
            split2(acc[mi][nj][3], h2.y, l2.y);
            *(__nv_bfloat162*)(oh + obase + (long)(r+8)*Dd + c) = h2;
            *(__nv_bfloat162*)(ol + obase + (long)(r+8)*Dd + c) = l2;
        }
    }
}

// ================= split conversions =======================================
__global__ __launch_bounds__(256) void split_act(
    const float* __restrict__ x, __nv_bfloat16* __restrict__ h,
    __nv_bfloat16* __restrict__ l)
{
    const int i = blockIdx.x * 256 + threadIdx.x;
    const float v = x[i];
    __nv_bfloat16 hi, lo; split2(v, hi, lo);
    h[i] = hi; l[i] = lo;
}

// W [K][N] fp32 -> Wt hi/lo bf16 [N][K]
__global__ __launch_bounds__(256) void split_wt(
    const float* __restrict__ W, int Kdim, int Ndim,
    __nv_bfloat16* __restrict__ h, __nv_bfloat16* __restrict__ l)
{
    __shared__ float t[32][33];
    const int tx = threadIdx.x, ty = threadIdx.y;
    const int n0 = blockIdx.x * 32, k0 = blockIdx.y * 32;
#pragma unroll
    for (int j = 0; j < 4; j++)
        t[ty + 8 * j][tx] = W[(long)(k0 + ty + 8 * j) * Ndim + n0 + tx];
    __syncthreads();
#pragma unroll
    for (int j = 0; j < 4; j++) {
        const float v = t[tx][ty + 8 * j];
        __nv_bfloat16 hi, lo; split2(v, hi, lo);
        const long oidx = (long)(n0 + ty + 8 * j) * Kdim + k0 + tx;
        h[oidx] = hi; l[oidx] = lo;
    }
}

// v pair [b*1024+s][h*64+e] -> vT pair [(b*8+h)*64+e][s]
__global__ void vtrans(
    const __nv_bfloat16* __restrict__ vh, const __nv_bfloat16* __restrict__ vl,
    __nv_bfloat16* __restrict__ vth, __nv_bfloat16* __restrict__ vtl)
{
    __shared__ __nv_bfloat16 th[32][33], tl[32][33];
    const int tx = threadIdx.x, ty = threadIdx.y;   // (32, 8)
    const int bh = blockIdx.z;
    const int b = bh >> 3, h = bh & 7;
    const int s0 = blockIdx.x * 32, e0 = blockIdx.y * 32;
    const long ibase = (long)b*Ll*Dd + h*Ee;
#pragma unroll
    for (int j = 0; j < 4; j++) {
        const long off = ibase + (long)(s0 + ty + 8*j)*Dd + e0 + tx;
        th[ty+8*j][tx] = vh[off];
        tl[ty+8*j][tx] = vl[off];
    }
    __syncthreads();
    const long obase = (long)bh*Ee*Ll;
#pragma unroll
    for (int j = 0; j < 4; j++) {
        const long off = obase + (long)(e0 + ty + 8*j)*Ll + s0 + tx;
        vth[off] = th[tx][ty+8*j];
        vtl[off] = tl[tx][ty+8*j];
    }
}

// ------- softmax rows of 1024 (float4 I/O), in place + bf16 pair output ----
__global__ __launch_bounds__(256) void softmax_split(
    float* __restrict__ a, __nv_bfloat16* __restrict__ ah,
    __nv_bfloat16* __restrict__ al)
{
    const long row = blockIdx.x;
    float* p = a + row * (long)Ll;
    __nv_bfloat16* ph = ah + row * (long)Ll;
    __nv_bfloat16* pl = al + row * (long)Ll;
    const int tid = threadIdx.x;

    float4 v4 = *(float4*)(p + tid * 4);
    float m = fmaxf(fmaxf(v4.x, v4.y), fmaxf(v4.z, v4.w));
#pragma unroll
    for (int off=16; off; off>>=1) m = fmaxf(m, __shfl_xor_sync(0xffffffffu, m, off));
    __shared__ float sm[8], ss[8];
    const int w = tid >> 5, lane = tid & 31;
    if (lane==0) sm[w] = m;
    __syncthreads();
    m = sm[0];
#pragma unroll
    for (int i=1;i<8;i++) m = fmaxf(m, sm[i]);
    v4.x = __expf(v4.x - m); v4.y = __expf(v4.y - m);
    v4.z = __expf(v4.z - m); v4.w = __expf(v4.w - m);
    float s = v4.x + v4.y + v4.z + v4.w;
#pragma unroll
    for (int off=16; off; off>>=1) s += __shfl_xor_sync(0xffffffffu, s, off);
    if (lane==0) ss[w] = s;
    __syncthreads();
    s = 0.f;
#pragma unroll
    for (int i=0;i<8;i++) s += ss[i];
    const float inv = 1.f / s;
    v4.x *= inv; v4.y *= inv; v4.z *= inv; v4.w *= inv;
    *(float4*)(p + tid * 4) = v4;
    __nv_bfloat162 h01, l01, h23, l23;
    split2(v4.x, h01.x, l01.x); split2(v4.y, h01.y, l01.y);
    split2(v4.z, h23.x, l23.x); split2(v4.w, h23.y, l23.y);
    *(__nv_bfloat162*)(ph + tid*4)     = h01;
    *(__nv_bfloat162*)(ph + tid*4 + 2) = h23;
    *(__nv_bfloat162*)(pl + tid*4)     = l01;
    *(__nv_bfloat162*)(pl + tid*4 + 2) = l23;
}

// ---------------- out = LayerNorm(xa + xb) (+ optional bf16 pair) ----------
__global__ __launch_bounds__(128) void add_ln(
    const float* __restrict__ xa, const float* __restrict__ xb,
    const float* __restrict__ g, const float* __restrict__ bt,
    float* __restrict__ out, __nv_bfloat16* __restrict__ oh,
    __nv_bfloat16* __restrict__ ol)
{
    const int row = blockIdx.x, tid = threadIdx.x;
    const float* pa = xa + (long)row*Dd;
    const float* pb = xb + (long)row*Dd;
    float v[4]; float s1=0.f, s2=0.f;
#pragma unroll
    for (int i=0;i<4;i++){ int c = tid + 128*i; v[i] = pa[c] + pb[c]; s1 += v[i]; s2 += v[i]*v[i]; }
#pragma unroll
    for (int off=16; off; off>>=1){
        s1 += __shfl_xor_sync(0xffffffffu, s1, off);
        s2 += __shfl_xor_sync(0xffffffffu, s2, off);
    }
    __shared__ float r1[4], r2[4];
    const int w = tid >> 5, lane = tid & 31;
    if (lane==0){ r1[w]=s1; r2[w]=s2; }
    __syncthreads();
    s1 = r1[0]+r1[1]+r1[2]+r1[3];
    s2 = r2[0]+r2[1]+r2[2]+r2[3];
    const float mean = s1 * (1.f/Dd);
    const float var  = s2 * (1.f/Dd) - mean*mean;
    const float rstd = rsqrtf(var + 1e-5f);
    float* po = out + (long)row*Dd;
#pragma unroll
    for (int i=0;i<4;i++){
        const int c = tid + 128*i;
        const float val = (v[i]-mean)*rstd*g[c] + bt[c];
        po[c] = val;
        if (oh) {
            __nv_bfloat16 hi, lo; split2(val, hi, lo);
            oh[(long)row*Dd + c] = hi;
            ol[(long)row*Dd + c] = lo;
        }
    }
}

// ============ 64x64 GEMM for small N problems (Wx, Wdt) ====================
__global__ __launch_bounds__(256) void gemm64(
    const float* __restrict__ A, int lda,
    const float* __restrict__ W, int ldw,
    const float* __restrict__ bias,
    float* __restrict__ C, int ldc, int K, int act)
{
    __shared__ float As[16][64];
    __shared__ float Ws[16][68];
    const int tid = threadIdx.x;
    const int row0 = blockIdx.y * 64;
    const int col0 = blockIdx.x * 64;
    const int ar = tid >> 2, ac = (tid & 3) * 4;
    const int br = tid >> 4, bc = (tid & 15) * 4;
    const int tm = (tid & 15) * 4, tn = (tid >> 4) * 4;
    float acc[4][4];
#pragma unroll
    for (int i=0;i<4;i++)
#pragma unroll
        for (int j=0;j<4;j++) acc[i][j]=0.f;

    for (int k0 = 0; k0 < K; k0 += 16) {
        float4 a4 = *(const float4*)(A + (long)(row0+ar)*lda + k0 + ac);
        As[ac+0][ar]=a4.x; As[ac+1][ar]=a4.y; As[ac+2][ar]=a4.z; As[ac+3][ar]=a4.w;
        float4 b4 = *(const float4*)(W + (long)(k0+br)*ldw + col0 + bc);
        *(float4*)&Ws[br][bc] = b4;
        __syncthreads();
#pragma unroll
        for (int k=0;k<16;k++){
            float a[4], b[4];
#pragma unroll
            for (int i=0;i<4;i++) a[i]=As[k][tm+i];
#pragma unroll
            for (int j=0;j<4;j++) b[j]=Ws[k][tn+j];
#pragma unroll
            for (int i=0;i<4;i++)
#pragma unroll
                for (int j=0;j<4;j++) acc[i][j]=fmaf(a[i],b[j],acc[i][j]);
        }
        __syncthreads();
    }
#pragma unroll
    for (int j=0;j<4;j++){
        int c = col0 + tn + j;
        float bvv = bias ? bias[c] : 0.f;
#pragma unroll
        for (int i=0;i<4;i++){
            float vv = acc[i][j] + bvv;
            if (act == 1) vv = (vv > 20.f) ? vv : log1pf(__expf(vv));
            C[(long)(row0+tm+i)*ldc + c] = vv;
        }
    }
}

// ---------------- depthwise causal conv (K=4) + bias + silu ----------------
__global__ __launch_bounds__(256) void conv_silu_k(
    const float* __restrict__ xz, const float* __restrict__ w,
    const float* __restrict__ cb, float* __restrict__ xc)
{
    const long idx = (long)blockIdx.x*256 + threadIdx.x;
    const int d = (int)(idx & (DINc-1));
    const long row = idx >> 10;
    const int l = (int)(row & (Ll-1));
    float acc = cb[d];
#pragma unroll
    for (int j=0;j<4;j++) {
        int ll = l - 3 + j;
        if (ll >= 0)
            acc = fmaf(xz[(row-3+j)*(2*DINc) + d], w[d*4+j], acc);
    }
    xc[idx] = acc / (1.f + __expf(-acc));
}

// ---------- selective scan, depth-8 load pipeline, bf16 pair output --------
#define PFD 8
__global__ __launch_bounds__(128) void scan_k(
    const float* __restrict__ dt, const float* __restrict__ xc,
    const float* __restrict__ dbl, const float* __restrict__ xz,
    const float* __restrict__ Alog, const float* __restrict__ Dp,
    __nv_bfloat16* __restrict__ yh, __nv_bfloat16* __restrict__ yl)
{
    const int tid = threadIdx.x;
    const int n  = tid & 15;
    const int dl = tid >> 4;
    const int b  = blockIdx.x >> 7;
    const int d  = (blockIdx.x & 127)*8 + dl;
    const float Aa = -__expf(Alog[d*Nn + n]);
    const float Dv = Dp[d];
    float h = 0.f;
    const long base = (long)b * Ll;

    float rdt[PFD], rxc[PFD], rB[PFD], rC[PFD], rz[PFD];
#pragma unroll
    for (int i = 0; i < PFD; i++) {
        const long r = base + i;
        rdt[i] = dt[r*DINc + d];
        rxc[i] = xc[r*DINc + d];
        rB[i]  = dbl[r*64 + 32 + n];
        rC[i]  = dbl[r*64 + 48 + n];
        rz[i]  = xz[r*(2*DINc) + DINc + d];
    }

    for (int t0 = 0; t0 < Ll; t0 += PFD) {
        float ndt[PFD], nxc[PFD], nB[PFD], nC[PFD], nz[PFD];
        const bool more = (t0 + PFD) < Ll;
        if (more) {
#pragma unroll
            for (int i = 0; i < PFD; i++) {
                const long r = base + t0 + PFD + i;
                ndt[i] = dt[r*DINc + d];
                nxc[i] = xc[r*DINc + d];
                nB[i]  = dbl[r*64 + 32 + n];
                nC[i]  = dbl[r*64 + 48 + n];
                nz[i]  = xz[r*(2*DINc) + DINc + d];
            }
        }
#pragma unroll
        for (int i = 0; i < PFD; i++) {
            const float dA = __expf(rdt[i] * Aa);
            h = fmaf(h, dA, rdt[i] * rxc[i] * rB[i]);
            float p = h * rC[i];
            p += __shfl_xor_sync(0xffffffffu, p, 8);
            p += __shfl_xor_sync(0xffffffffu, p, 4);
            p += __shfl_xor_sync(0xffffffffu, p, 2);
            p += __shfl_xor_sync(0xffffffffu, p, 1);
            if (n == 0) {
                const float sz = rz[i] / (1.f + __expf(-rz[i]));
                const float val = (p + rxc[i] * Dv) * sz;
                __nv_bfloat16 hi, lo; split2(val, hi, lo);
                yh[(base + t0 + i)*DINc + d] = hi;
                yl[(base + t0 + i)*DINc + d] = lo;
            }
        }
        if (more) {
#pragma unroll
            for (int i = 0; i < PFD; i++) {
                rdt[i]=ndt[i]; rxc[i]=nxc[i]; rB[i]=nB[i]; rC[i]=nC[i]; rz[i]=nz[i];
            }
        }
    }
}

// ---------------- launch ----------------------------------------------------
extern "C" void kernel_launch(void* const* d_in, const int* in_sizes, int n_in,
                              void* d_out, int out_size)
{
    const float* x    = (const float*)d_in[0];
    const float* Wq   = (const float*)d_in[1];
    const float* bq   = (const float*)d_in[2];
    const float* Wk   = (const float*)d_in[3];
    const float* bk   = (const float*)d_in[4];
    const float* Wv   = (const float*)d_in[5];
    const float* bv   = (const float*)d_in[6];
    const float* Wo   = (const float*)d_in[7];
    const float* bo   = (const float*)d_in[8];
    const float* ln1g = (const float*)d_in[9];
    const float* ln1b = (const float*)d_in[10];
    const float* ln2g = (const float*)d_in[11];
    const float* ln2b = (const float*)d_in[12];
    const float* Win  = (const float*)d_in[13];
    const float* cw   = (const float*)d_in[14];
    const float* cb   = (const float*)d_in[15];
    const float* Wx   = (const float*)d_in[16];
    const float* Wdt  = (const float*)d_in[17];
    const float* bdt  = (const float*)d_in[18];
    const float* Alog = (const float*)d_in[19];
    const float* Dp   = (const float*)d_in[20];
    const float* Wout = (const float*)d_in[21];

    float* out  = (float*)d_out;
    float* attn = out + (size_t)Bb*Ll*Dd;

    float *t1,*x1,*xz,*xc,*db,*dtb,*y;
    cudaGetSymbolAddress((void**)&t1, g_t1);
    cudaGetSymbolAddress((void**)&x1, g_x1);
    cudaGetSymbolAddress((void**)&xz, g_xz);
    cudaGetSymbolAddress((void**)&xc, g_xc);
    cudaGetSymbolAddress((void**)&db, g_db);
    cudaGetSymbolAddress((void**)&dtb,g_dt);
    cudaGetSymbolAddress((void**)&y,  g_y);

    __nv_bfloat16 *xh,*xl,*qh,*ql,*kh,*kl,*vh,*vl,*vth,*vtl,*ah,*al,*oh,*ol,*x1h,*x1l,*yah,*yal;
    __nv_bfloat16 *Wqh,*Wql,*Wkh,*Wkl,*Wvh,*Wvl,*Woh,*Wol,*Wih,*Wil,*Wuh,*Wul;
    cudaGetSymbolAddress((void**)&xh,  g_xh);  cudaGetSymbolAddress((void**)&xl,  g_xl);
    cudaGetSymbolAddress((void**)&qh,  g_qh);  cudaGetSymbolAddress((void**)&ql,  g_ql);
    cudaGetSymbolAddress((void**)&kh,  g_kh);  cudaGetSymbolAddress((void**)&kl,  g_kl);
    cudaGetSymbolAddress((void**)&vh,  g_vh);  cudaGetSymbolAddress((void**)&vl,  g_vl);
    cudaGetSymbolAddress((void**)&vth, g_vth); cudaGetSymbolAddress((void**)&vtl, g_vtl);
    cudaGetSymbolAddress((void**)&ah,  g_ah);  cudaGetSymbolAddress((void**)&al,  g_al);
    cudaGetSymbolAddress((void**)&oh,  g_oh);  cudaGetSymbolAddress((void**)&ol,  g_ol);
    cudaGetSymbolAddress((void**)&x1h, g_x1h); cudaGetSymbolAddress((void**)&x1l, g_x1l);
    cudaGetSymbolAddress((void**)&yah, g_yah); cudaGetSymbolAddress((void**)&yal, g_yal);
    cudaGetSymbolAddress((void**)&Wqh, g_Wqh); cudaGetSymbolAddress((void**)&Wql, g_Wql);
    cudaGetSymbolAddress((void**)&Wkh, g_Wkh); cudaGetSymbolAddress((void**)&Wkl, g_Wkl);
    cudaGetSymbolAddress((void**)&Wvh, g_Wvh); cudaGetSymbolAddress((void**)&Wvl, g_Wvl);
    cudaGetSymbolAddress((void**)&Woh, g_Woh); cudaGetSymbolAddress((void**)&Wol, g_Wol);
    cudaGetSymbolAddress((void**)&Wih, g_Wih); cudaGetSymbolAddress((void**)&Wil, g_Wil);
    cudaGetSymbolAddress((void**)&Wuh, g_Wuh); cudaGetSymbolAddress((void**)&Wul, g_Wul);

    // weight conversions (transpose + hi/lo split)
    split_wt<<<dim3(Dd/32, Dd/32), dim3(32,8)>>>(Wq, Dd, Dd, Wqh, Wql);
    split_wt<<<dim3(Dd/32, Dd/32), dim3(32,8)>>>(Wk, Dd, Dd, Wkh, Wkl);
    split_wt<<<dim3(Dd/32, Dd/32), dim3(32,8)>>>(Wv, Dd, Dd, Wvh, Wvl);
    split_wt<<<dim3(Dd/32, Dd/32), dim3(32,8)>>>(Wo, Dd, Dd, Woh, Wol);
    split_wt<<<dim3(2*DINc/32, Dd/32), dim3(32,8)>>>(Win, Dd, 2*DINc, Wih, Wil);
    split_wt<<<dim3(Dd/32, DINc/32), dim3(32,8)>>>(Wout, DINc, Dd, Wuh, Wul);

    // x split + QKV (mma, bf16-pair outputs)
    split_act<<<(Mrows*Dd)/256, 256>>>(x, xh, xl);
    gemm_mma<<<dim3(Dd/128, Mrows/128), 256>>>(xh, xl, Wqh, Wql, bq, nullptr, qh, ql, Dd, Dd);
    gemm_mma<<<dim3(Dd/128, Mrows/128), 256>>>(xh, xl, Wkh, Wkl, bk, nullptr, kh, kl, Dd, Dd);
    gemm_mma<<<dim3(Dd/128, Mrows/128), 256>>>(xh, xl, Wvh, Wvl, bv, nullptr, vh, vl, Dd, Dd);
    vtrans<<<dim3(Ll/32, Ee/32, Bb*Hh), dim3(32,8)>>>(vh, vl, vth, vtl);

    // attention
    scores_mma<<<dim3(Ll/128, Ll/128, Bb*Hh), 256>>>(qh, ql, kh, kl, attn);
    softmax_split<<<Bb*Hh*Ll, 256>>>(attn, ah, al);
    attnv_mma<<<dim3(1, Ll/128, Bb*Hh), 256>>>(ah, al, vth, vtl, oh, ol);

    // o @ Wo + bo (mma) ; x1 = LN(x + .) with pair output
    gemm_mma<<<dim3(Dd/128, Mrows/128), 256>>>(oh, ol, Woh, Wol, bo, t1, nullptr, nullptr, Dd, Dd);
    add_ln<<<Mrows, 128>>>(x, t1, ln1g, ln1b, x1, x1h, x1l);

    // mamba in-proj (mma, N=2048)
    gemm_mma<<<dim3(2*DINc/128, Mrows/128), 256>>>(x1h, x1l, Wih, Wil, nullptr, xz, nullptr, nullptr, 2*DINc, Dd);

    // conv + silu
    conv_silu_k<<<(Mrows*DINc)/256, 256>>>(xz, cw, cb, xc);
    // dbl = xc @ Wx   (N=64, K=1024)
    gemm64<<<dim3(1, Mrows/64), 256>>>(xc, DINc, Wx, 64, nullptr, db, 64, DINc, 0);
    // dt = softplus(dbl[:, :32] @ Wdt + bdt)
    gemm64<<<dim3(DINc/64, Mrows/64), 256>>>(db, 64, Wdt, DINc, bdt, dtb, DINc, Rr, 1);
    // selective scan -> ya bf16 pair
    scan_k<<<Bb*(DINc/8), 128>>>(dtb, xc, db, xz, Alog, Dp, yah, yal);

    // out-proj (mma, K=1024) + final LN
    gemm_mma<<<dim3(Dd/128, Mrows/128), 256>>>(yah, yal, Wuh, Wul, nullptr, y, nullptr, nullptr, Dd, DINc);
    add_ln<<<Mrows, 128>>>(x1, y, ln2g, ln2b, out, nullptr, nullptr);

    (void)in_sizes; (void)n_in; (void)out_size;
}